// round 1
// baseline (speedup 1.0000x reference)
#include <cuda_runtime.h>

// Problem constants: B=1, N=4096, C=1024, H=16, HD=64
#define SEQ  4096
#define CDIM 1024
#define NH   16
#define HDIM 64

// Scratch (allocation-free rule: __device__ globals)
__device__ float g_qkv[SEQ * 2 * CDIM];   // (n, 2, H, HD) flattened: 32 MB
__device__ float g_att[SEQ * CDIM];       // attention output (n, h*64+d): 16 MB

// ---------------------------------------------------------------------------
// Classic 128x128x8 fp32 SGEMM, 256 threads, 8x8 register tile per thread.
// C = A(MxK) @ B(KxN) [+ bias]
// ---------------------------------------------------------------------------
template <bool HAS_BIAS>
__global__ void __launch_bounds__(256)
sgemm_kernel(const float* __restrict__ A, const float* __restrict__ B,
             const float* __restrict__ bias, float* __restrict__ C,
             int M, int N, int K)
{
    const int BM = 128, BN = 128, BK = 8;
    __shared__ float As[BK][BM];
    __shared__ float Bs[BK][BN];

    int tid = threadIdx.x;
    int tx = tid & 15;       // 0..15 -> 8 cols each
    int ty = tid >> 4;       // 0..15 -> 8 rows each
    int bx = blockIdx.x;     // N tiles
    int by = blockIdx.y;     // M tiles

    const float* Ab = A + (size_t)(by * BM) * K;
    const float* Bb = B + (size_t)(bx * BN);

    int aRow = tid >> 1;          // 0..127
    int aCol = (tid & 1) * 4;     // 0 or 4
    int bRow = tid >> 5;          // 0..7
    int bCol = (tid & 31) * 4;    // 0..124

    float acc[8][8];
    #pragma unroll
    for (int i = 0; i < 8; i++)
        #pragma unroll
        for (int j = 0; j < 8; j++) acc[i][j] = 0.f;

    for (int k0 = 0; k0 < K; k0 += BK) {
        float4 a4 = *(const float4*)(Ab + (size_t)aRow * K + k0 + aCol);
        As[aCol + 0][aRow] = a4.x;
        As[aCol + 1][aRow] = a4.y;
        As[aCol + 2][aRow] = a4.z;
        As[aCol + 3][aRow] = a4.w;
        *(float4*)&Bs[bRow][bCol] =
            *(const float4*)(Bb + (size_t)(k0 + bRow) * N + bCol);
        __syncthreads();

        #pragma unroll
        for (int k = 0; k < BK; k++) {
            float ar[8], br[8];
            *(float4*)&ar[0] = *(float4*)&As[k][ty * 8];
            *(float4*)&ar[4] = *(float4*)&As[k][ty * 8 + 4];
            *(float4*)&br[0] = *(float4*)&Bs[k][tx * 8];
            *(float4*)&br[4] = *(float4*)&Bs[k][tx * 8 + 4];
            #pragma unroll
            for (int i = 0; i < 8; i++)
                #pragma unroll
                for (int j = 0; j < 8; j++)
                    acc[i][j] += ar[i] * br[j];
        }
        __syncthreads();
    }

    float* Cb = C + (size_t)(by * BM) * N + (size_t)(bx * BN);
    #pragma unroll
    for (int i = 0; i < 8; i++) {
        int row = ty * 8 + i;
        #pragma unroll
        for (int j = 0; j < 8; j += 4) {
            int col = tx * 8 + j;
            float4 v;
            v.x = acc[i][j + 0];
            v.y = acc[i][j + 1];
            v.z = acc[i][j + 2];
            v.w = acc[i][j + 3];
            if (HAS_BIAS) {
                v.x += bias[bx * BN + col + 0];
                v.y += bias[bx * BN + col + 1];
                v.z += bias[bx * BN + col + 2];
                v.w += bias[bx * BN + col + 3];
            }
            *(float4*)(Cb + (size_t)row * N + col) = v;
        }
    }
}

// ---------------------------------------------------------------------------
// Flash attention, fp32. Per block: one head, 128 query rows; stream 64-key
// tiles. 128 threads, 8x8 fragments. tx = lane bits 0..2 (row reductions via
// shfl_xor 1/2/4). Smem rows padded to stride 65 (conflicts <= 2-way).
// ---------------------------------------------------------------------------
#define FBM 128
#define FBN 64
#define FPAD 65

__global__ void __launch_bounds__(128)
flash_kernel(const float* __restrict__ qkv, const float* __restrict__ x2,
             float* __restrict__ outb)
{
    extern __shared__ float sm[];
    float* Qs = sm;                      // FBM x FPAD
    float* Ks = Qs + FBM * FPAD;         // FBN x FPAD
    float* Vs = Ks + FBN * FPAD;         // FBN x FPAD
    float* Ps = Vs + FBN * FPAD;         // FBM x FPAD

    int tid = threadIdx.x;
    int tx = tid & 7;        // 0..7  -> 8 cols each
    int ty = tid >> 3;       // 0..15 -> 8 rows each
    int h  = blockIdx.y;
    int q0 = blockIdx.x * FBM;
    const float scale = 0.125f;  // 64^-0.5

    // Load Q tile (scaled). 128x64 floats = 2048 float4s, 16 per thread.
    #pragma unroll
    for (int r = 0; r < 16; r++) {
        int idx = r * 128 + tid;
        int row = idx >> 4;
        int dq  = (idx & 15) * 4;
        float4 v = *(const float4*)(qkv + (size_t)(q0 + row) * 2048 + h * 64 + dq);
        float* p = &Qs[row * FPAD + dq];
        p[0] = v.x * scale; p[1] = v.y * scale;
        p[2] = v.z * scale; p[3] = v.w * scale;
    }

    float accO[8][8];
    float m_i[8], l_i[8];
    #pragma unroll
    for (int i = 0; i < 8; i++) {
        m_i[i] = -1e30f;
        l_i[i] = 0.f;
        #pragma unroll
        for (int d = 0; d < 8; d++) accO[i][d] = 0.f;
    }

    for (int t = 0; t < SEQ / FBN; t++) {
        __syncthreads();  // previous O-phase readers of Ks/Vs/Ps done
        int kv0 = t * FBN;
        // Load K and V tiles: 64x64 each = 1024 quads, 8 per thread.
        #pragma unroll
        for (int r = 0; r < 8; r++) {
            int idx = r * 128 + tid;
            int row = idx >> 4;
            int dq  = (idx & 15) * 4;
            float4 kv = *(const float4*)(qkv + (size_t)(kv0 + row) * 2048 + 1024 + h * 64 + dq);
            float* pk = &Ks[row * FPAD + dq];
            pk[0] = kv.x; pk[1] = kv.y; pk[2] = kv.z; pk[3] = kv.w;
            float4 vv = *(const float4*)(x2 + (size_t)(kv0 + row) * 1024 + h * 64 + dq);
            float* pv = &Vs[row * FPAD + dq];
            pv[0] = vv.x; pv[1] = vv.y; pv[2] = vv.z; pv[3] = vv.w;
        }
        __syncthreads();

        // S = (Q*scale) @ K^T, 8x8 fragment per thread
        float accS[8][8];
        #pragma unroll
        for (int i = 0; i < 8; i++)
            #pragma unroll
            for (int j = 0; j < 8; j++) accS[i][j] = 0.f;

        #pragma unroll 8
        for (int d = 0; d < HDIM; d++) {
            float ar[8], br[8];
            #pragma unroll
            for (int i = 0; i < 8; i++) ar[i] = Qs[(ty * 8 + i) * FPAD + d];
            #pragma unroll
            for (int j = 0; j < 8; j++) br[j] = Ks[(tx * 8 + j) * FPAD + d];
            #pragma unroll
            for (int i = 0; i < 8; i++)
                #pragma unroll
                for (int j = 0; j < 8; j++)
                    accS[i][j] += ar[i] * br[j];
        }

        // Online softmax (row reduction over tx = lane bits 0..2)
        #pragma unroll
        for (int i = 0; i < 8; i++) {
            float mx = accS[i][0];
            #pragma unroll
            for (int j = 1; j < 8; j++) mx = fmaxf(mx, accS[i][j]);
            mx = fmaxf(mx, __shfl_xor_sync(0xffffffffu, mx, 1));
            mx = fmaxf(mx, __shfl_xor_sync(0xffffffffu, mx, 2));
            mx = fmaxf(mx, __shfl_xor_sync(0xffffffffu, mx, 4));
            float mnew = fmaxf(m_i[i], mx);
            float corr = __expf(m_i[i] - mnew);
            m_i[i] = mnew;
            float s = 0.f;
            #pragma unroll
            for (int j = 0; j < 8; j++) {
                float p = __expf(accS[i][j] - mnew);
                accS[i][j] = p;
                s += p;
            }
            s += __shfl_xor_sync(0xffffffffu, s, 1);
            s += __shfl_xor_sync(0xffffffffu, s, 2);
            s += __shfl_xor_sync(0xffffffffu, s, 4);
            l_i[i] = l_i[i] * corr + s;
            #pragma unroll
            for (int d = 0; d < 8; d++) accO[i][d] *= corr;
        }

        // Stage P through smem for the j-contraction
        #pragma unroll
        for (int i = 0; i < 8; i++)
            #pragma unroll
            for (int j = 0; j < 8; j++)
                Ps[(ty * 8 + i) * FPAD + tx * 8 + j] = accS[i][j];
        __syncthreads();

        // O += P @ V
        #pragma unroll 8
        for (int j = 0; j < FBN; j++) {
            float a[8], b[8];
            #pragma unroll
            for (int i = 0; i < 8; i++) a[i] = Ps[(ty * 8 + i) * FPAD + j];
            #pragma unroll
            for (int d = 0; d < 8; d++) b[d] = Vs[j * FPAD + tx * 8 + d];
            #pragma unroll
            for (int i = 0; i < 8; i++)
                #pragma unroll
                for (int d = 0; d < 8; d++)
                    accO[i][d] += a[i] * b[d];
        }
    }

    // Epilogue: normalize and write out[n][h*64+d]
    #pragma unroll
    for (int i = 0; i < 8; i++) {
        float inv = 1.0f / l_i[i];
        int n = q0 + ty * 8 + i;
        #pragma unroll
        for (int j = 0; j < 8; j += 4) {
            int dd = tx * 8 + j;
            float4 v;
            v.x = accO[i][j + 0] * inv;
            v.y = accO[i][j + 1] * inv;
            v.z = accO[i][j + 2] * inv;
            v.w = accO[i][j + 3] * inv;
            *(float4*)(outb + (size_t)n * CDIM + h * 64 + dd) = v;
        }
    }
}

// ---------------------------------------------------------------------------
extern "C" void kernel_launch(void* const* d_in, const int* in_sizes, int n_in,
                              void* d_out, int out_size)
{
    const float* x1     = (const float*)d_in[0];
    const float* x2     = (const float*)d_in[1];
    const float* W_qkv  = (const float*)d_in[2];
    const float* W_proj = (const float*)d_in[3];
    const float* b_proj = (const float*)d_in[4];
    float* out = (float*)d_out;

    float* qkv = nullptr;
    float* att = nullptr;
    cudaGetSymbolAddress((void**)&qkv, g_qkv);
    cudaGetSymbolAddress((void**)&att, g_att);

    // 1) qkv = x1 @ W_qkv : (4096 x 1024) @ (1024 x 2048)
    {
        dim3 grid(2 * CDIM / 128, SEQ / 128);
        sgemm_kernel<false><<<grid, 256>>>(x1, W_qkv, nullptr, qkv,
                                           SEQ, 2 * CDIM, CDIM);
    }

    // 2) flash attention per head
    {
        int smem = (FBM * FPAD + 2 * FBN * FPAD + FBM * FPAD) * (int)sizeof(float);
        cudaFuncSetAttribute(flash_kernel,
                             cudaFuncAttributeMaxDynamicSharedMemorySize, smem);
        dim3 grid(SEQ / FBM, NH);
        flash_kernel<<<grid, 128, smem>>>(qkv, x2, att);
    }

    // 3) out = att @ W_proj + b_proj : (4096 x 1024) @ (1024 x 1024)
    {
        dim3 grid(CDIM / 128, SEQ / 128);
        sgemm_kernel<true><<<grid, 256>>>(att, W_proj, b_proj, out,
                                          SEQ, CDIM, CDIM);
    }
}

// round 2
// speedup vs baseline: 2.3422x; 2.3422x over previous
#include <cuda_runtime.h>
#include <cstdint>

#define SEQ  4096
#define CDIM 1024
#define NH   16
#define HDIM 64

// Scratch (allocation-free rule)
__device__ float g_qkv[SEQ * 2 * CDIM];
__device__ float g_att[SEQ * CDIM];

// ---------------------------------------------------------------------------
// helpers
// ---------------------------------------------------------------------------
__device__ __forceinline__ uint32_t f2tf(float x) {
    uint32_t r;
    asm("cvt.rna.tf32.f32 %0, %1;" : "=r"(r) : "f"(x));
    return r;
}

__device__ __forceinline__ void mma8(float* d, const uint32_t* a, const uint32_t* b) {
    asm volatile(
        "mma.sync.aligned.m16n8k8.row.col.f32.tf32.tf32.f32 "
        "{%0,%1,%2,%3}, {%4,%5,%6,%7}, {%8,%9}, {%0,%1,%2,%3};\n"
        : "+f"(d[0]), "+f"(d[1]), "+f"(d[2]), "+f"(d[3])
        : "r"(a[0]), "r"(a[1]), "r"(a[2]), "r"(a[3]), "r"(b[0]), "r"(b[1]));
}

__device__ __forceinline__ void cpasync16(float* smem_dst, const float* gsrc) {
    uint32_t s = (uint32_t)__cvta_generic_to_shared(smem_dst);
    asm volatile("cp.async.cg.shared.global [%0], [%1], 16;\n" :: "r"(s), "l"(gsrc));
}

// ---------------------------------------------------------------------------
// 3-pass TF32 GEMM (near-fp32 accuracy): C = A @ B (+bias)
// 128x128 block, BK=16, 8 warps (2x4), warp tile 64x32, mma m16n8k8.
// ---------------------------------------------------------------------------
template <bool HAS_BIAS>
__global__ void __launch_bounds__(256)
tgemm3(const float* __restrict__ A, const float* __restrict__ B,
       const float* __restrict__ bias, float* __restrict__ C,
       int M, int N, int K)
{
    const int LDA = 20;    // A smem [128][20]  (conflict-free frag reads)
    const int LDB = 136;   // B smem [16][136]
    __shared__ float As[2][128 * LDA];
    __shared__ float Bs[2][16 * LDB];

    int tid  = threadIdx.x;
    int lane = tid & 31, wid = tid >> 5;
    int g = lane >> 2, tig = lane & 3;
    int warpM = wid >> 2, warpN = wid & 3;
    int bm0 = blockIdx.y * 128, bn0 = blockIdx.x * 128;

    float acc[4][4][4];
    #pragma unroll
    for (int a = 0; a < 4; a++)
        #pragma unroll
        for (int b = 0; b < 4; b++)
            #pragma unroll
            for (int c = 0; c < 4; c++) acc[a][b][c] = 0.f;

    const int NT = K / 16;

    // tile loader (cp.async)
    auto load_tile = [&](int buf, int k0) {
        #pragma unroll
        for (int i = 0; i < 2; i++) {
            int c = tid + i * 256;
            int r = c >> 2, cc = (c & 3) * 4;
            cpasync16(&As[buf][r * LDA + cc], A + (size_t)(bm0 + r) * K + k0 + cc);
        }
        #pragma unroll
        for (int i = 0; i < 2; i++) {
            int c = tid + i * 256;
            int r = c >> 5, cc = (c & 31) * 4;
            cpasync16(&Bs[buf][r * LDB + cc], B + (size_t)(k0 + r) * N + bn0 + cc);
        }
        asm volatile("cp.async.commit_group;\n");
    };

    load_tile(0, 0);

    for (int kt = 0; kt < NT; kt++) {
        int cur = kt & 1;
        if (kt + 1 < NT) {
            load_tile(cur ^ 1, (kt + 1) * 16);
            asm volatile("cp.async.wait_group 1;\n");
        } else {
            asm volatile("cp.async.wait_group 0;\n");
        }
        __syncthreads();

        const float* as = As[cur];
        const float* bs = Bs[cur];

        #pragma unroll
        for (int kk = 0; kk < 16; kk += 8) {
            uint32_t ah[4][4], al[4][4];
            #pragma unroll
            for (int mt = 0; mt < 4; mt++) {
                int rb = warpM * 64 + mt * 16;
                #pragma unroll
                for (int q = 0; q < 4; q++) {
                    int r = rb + g + (q & 1) * 8;
                    int c = kk + tig + (q >> 1) * 4;
                    float x = as[r * LDA + c];
                    uint32_t h = f2tf(x);
                    ah[mt][q] = h;
                    al[mt][q] = f2tf(x - __uint_as_float(h));
                }
            }
            uint32_t bh[4][2], bl[4][2];
            #pragma unroll
            for (int nt = 0; nt < 4; nt++) {
                int col = warpN * 32 + nt * 8 + g;
                #pragma unroll
                for (int q = 0; q < 2; q++) {
                    float x = bs[(kk + tig + q * 4) * LDB + col];
                    uint32_t h = f2tf(x);
                    bh[nt][q] = h;
                    bl[nt][q] = f2tf(x - __uint_as_float(h));
                }
            }
            #pragma unroll
            for (int mt = 0; mt < 4; mt++)
                #pragma unroll
                for (int nt = 0; nt < 4; nt++) {
                    mma8(acc[mt][nt], al[mt], bh[nt]);  // lo*hi
                    mma8(acc[mt][nt], ah[mt], bl[nt]);  // hi*lo
                    mma8(acc[mt][nt], ah[mt], bh[nt]);  // hi*hi
                }
        }
        __syncthreads();
    }

    // epilogue
    #pragma unroll
    for (int mt = 0; mt < 4; mt++) {
        int row0 = bm0 + warpM * 64 + mt * 16 + g;
        #pragma unroll
        for (int nt = 0; nt < 4; nt++) {
            int col = bn0 + warpN * 32 + nt * 8 + 2 * tig;
            float b0 = 0.f, b1 = 0.f;
            if (HAS_BIAS) { b0 = bias[col]; b1 = bias[col + 1]; }
            float2 v0 = { acc[mt][nt][0] + b0, acc[mt][nt][1] + b1 };
            float2 v1 = { acc[mt][nt][2] + b0, acc[mt][nt][3] + b1 };
            *(float2*)(C + (size_t)row0 * N + col) = v0;
            *(float2*)(C + (size_t)(row0 + 8) * N + col) = v1;
        }
    }
}

// ---------------------------------------------------------------------------
// Flash attention with TF32 mma. Block: 4 warps, 128 Q rows (32/warp),
// 64-key tiles. K smem stride 68 (conflict-free), V XOR-swizzled 64x64.
// P is transposed C-frag -> A-frag in-register via width-4 shuffles.
// ---------------------------------------------------------------------------
__global__ void __launch_bounds__(128)
flash_mma(const float* __restrict__ qkv, const float* __restrict__ x2,
          float* __restrict__ outb)
{
    extern __shared__ float sm[];
    float* Qs = sm;               // 128 x 68
    float* Ks = Qs + 128 * 68;    // 64 x 68
    float* Vs = Ks + 64 * 68;     // 64 x 64 (swizzled)

    int tid  = threadIdx.x;
    int lane = tid & 31, wid = tid >> 5;
    int g = lane >> 2, tig = lane & 3;
    int h  = blockIdx.y;
    int q0 = blockIdx.x * 128;
    int wr = wid * 32;

    // load Q (pre-scaled by 1/sqrt(64))
    #pragma unroll
    for (int i = 0; i < 16; i++) {
        int idx = i * 128 + tid;
        int r = idx >> 4, c4 = (idx & 15) * 4;
        float4 v = *(const float4*)(qkv + (size_t)(q0 + r) * 2048 + h * 64 + c4);
        float* p = &Qs[r * 68 + c4];
        p[0] = v.x * 0.125f; p[1] = v.y * 0.125f;
        p[2] = v.z * 0.125f; p[3] = v.w * 0.125f;
    }

    float m_i[4], l_i[4], accO[2][8][4];
    #pragma unroll
    for (int i = 0; i < 4; i++) { m_i[i] = -1e30f; l_i[i] = 0.f; }
    #pragma unroll
    for (int mt = 0; mt < 2; mt++)
        #pragma unroll
        for (int dn = 0; dn < 8; dn++)
            #pragma unroll
            for (int c = 0; c < 4; c++) accO[mt][dn][c] = 0.f;

    const int src0 = tig >> 1;
    const bool odd = tig & 1;

    for (int t = 0; t < SEQ / 64; t++) {
        __syncthreads();   // prior tile fully consumed (also guards Q at t=0)
        int kv0 = t * 64;
        #pragma unroll
        for (int i = 0; i < 8; i++) {
            int idx = i * 128 + tid;
            int r = idx >> 4, c4 = (idx & 15) * 4;
            float4 kvv = *(const float4*)(qkv + (size_t)(kv0 + r) * 2048 + 1024 + h * 64 + c4);
            *(float4*)&Ks[r * 68 + c4] = kvv;
            float4 vv = *(const float4*)(x2 + (size_t)(kv0 + r) * 1024 + h * 64 + c4);
            int sc = c4 ^ ((r & 7) << 3);
            *(float4*)&Vs[r * 64 + sc] = vv;
        }
        __syncthreads();

        // ---- S = Q @ K^T (32 x 64 per warp) ----
        float s[2][8][4];
        #pragma unroll
        for (int mt = 0; mt < 2; mt++)
            #pragma unroll
            for (int nt = 0; nt < 8; nt++)
                #pragma unroll
                for (int c = 0; c < 4; c++) s[mt][nt][c] = 0.f;

        #pragma unroll
        for (int kc = 0; kc < 8; kc++) {
            uint32_t qa[2][4];
            #pragma unroll
            for (int mt = 0; mt < 2; mt++) {
                int rb = wr + mt * 16;
                qa[mt][0] = f2tf(Qs[(rb + g)     * 68 + kc * 8 + tig]);
                qa[mt][1] = f2tf(Qs[(rb + 8 + g) * 68 + kc * 8 + tig]);
                qa[mt][2] = f2tf(Qs[(rb + g)     * 68 + kc * 8 + tig + 4]);
                qa[mt][3] = f2tf(Qs[(rb + 8 + g) * 68 + kc * 8 + tig + 4]);
            }
            #pragma unroll
            for (int nt = 0; nt < 8; nt++) {
                uint32_t kb[2];
                kb[0] = f2tf(Ks[(nt * 8 + g) * 68 + kc * 8 + tig]);
                kb[1] = f2tf(Ks[(nt * 8 + g) * 68 + kc * 8 + tig + 4]);
                mma8(s[0][nt], qa[0], kb);
                mma8(s[1][nt], qa[1], kb);
            }
        }

        // ---- online softmax (rows live on 4-lane groups: shfl_xor 1,2) ----
        #pragma unroll
        for (int mt = 0; mt < 2; mt++)
            #pragma unroll
            for (int rg = 0; rg < 2; rg++) {
                int ri = mt * 2 + rg;
                float mx = -1e30f;
                #pragma unroll
                for (int nt = 0; nt < 8; nt++) {
                    mx = fmaxf(mx, s[mt][nt][2 * rg]);
                    mx = fmaxf(mx, s[mt][nt][2 * rg + 1]);
                }
                mx = fmaxf(mx, __shfl_xor_sync(0xffffffffu, mx, 1));
                mx = fmaxf(mx, __shfl_xor_sync(0xffffffffu, mx, 2));
                float mnew = fmaxf(m_i[ri], mx);
                float corr = __expf(m_i[ri] - mnew);
                m_i[ri] = mnew;
                float rs = 0.f;
                #pragma unroll
                for (int nt = 0; nt < 8; nt++) {
                    float p0 = __expf(s[mt][nt][2 * rg]     - mnew);
                    float p1 = __expf(s[mt][nt][2 * rg + 1] - mnew);
                    s[mt][nt][2 * rg]     = p0;
                    s[mt][nt][2 * rg + 1] = p1;
                    rs += p0 + p1;
                }
                rs += __shfl_xor_sync(0xffffffffu, rs, 1);
                rs += __shfl_xor_sync(0xffffffffu, rs, 2);
                l_i[ri] = l_i[ri] * corr + rs;
                #pragma unroll
                for (int dn = 0; dn < 8; dn++) {
                    accO[mt][dn][2 * rg]     *= corr;
                    accO[mt][dn][2 * rg + 1] *= corr;
                }
            }

        // ---- O += P @ V ----
        #pragma unroll
        for (int kc = 0; kc < 8; kc++) {
            uint32_t pa[2][4];
            #pragma unroll
            for (int mt = 0; mt < 2; mt++) {
                float s0 = s[mt][kc][0], s1 = s[mt][kc][1];
                float s2 = s[mt][kc][2], s3 = s[mt][kc][3];
                float v00 = __shfl_sync(0xffffffffu, s0, src0, 4);
                float v10 = __shfl_sync(0xffffffffu, s1, src0, 4);
                float v20 = __shfl_sync(0xffffffffu, s2, src0, 4);
                float v30 = __shfl_sync(0xffffffffu, s3, src0, 4);
                float v01 = __shfl_sync(0xffffffffu, s0, src0 + 2, 4);
                float v11 = __shfl_sync(0xffffffffu, s1, src0 + 2, 4);
                float v21 = __shfl_sync(0xffffffffu, s2, src0 + 2, 4);
                float v31 = __shfl_sync(0xffffffffu, s3, src0 + 2, 4);
                pa[mt][0] = f2tf(odd ? v10 : v00);
                pa[mt][1] = f2tf(odd ? v30 : v20);
                pa[mt][2] = f2tf(odd ? v11 : v01);
                pa[mt][3] = f2tf(odd ? v31 : v21);
            }
            #pragma unroll
            for (int dn = 0; dn < 8; dn++) {
                uint32_t vb[2];
                int r0 = kc * 8 + tig, r1 = kc * 8 + tig + 4;
                vb[0] = f2tf(Vs[r0 * 64 + ((dn * 8 + g) ^ ((r0 & 7) << 3))]);
                vb[1] = f2tf(Vs[r1 * 64 + ((dn * 8 + g) ^ ((r1 & 7) << 3))]);
                mma8(accO[0][dn], pa[0], vb);
                mma8(accO[1][dn], pa[1], vb);
            }
        }
    }

    // ---- epilogue ----
    #pragma unroll
    for (int mt = 0; mt < 2; mt++)
        #pragma unroll
        for (int rg = 0; rg < 2; rg++) {
            int ri = mt * 2 + rg;
            float inv = 1.0f / l_i[ri];
            int r = q0 + wr + mt * 16 + g + rg * 8;
            #pragma unroll
            for (int dn = 0; dn < 8; dn++) {
                int col = h * 64 + dn * 8 + 2 * tig;
                float2 o = { accO[mt][dn][2 * rg] * inv,
                             accO[mt][dn][2 * rg + 1] * inv };
                *(float2*)(outb + (size_t)r * CDIM + col) = o;
            }
        }
}

// ---------------------------------------------------------------------------
extern "C" void kernel_launch(void* const* d_in, const int* in_sizes, int n_in,
                              void* d_out, int out_size)
{
    const float* x1     = (const float*)d_in[0];
    const float* x2     = (const float*)d_in[1];
    const float* W_qkv  = (const float*)d_in[2];
    const float* W_proj = (const float*)d_in[3];
    const float* b_proj = (const float*)d_in[4];
    float* out = (float*)d_out;

    float* qkv = nullptr;
    float* att = nullptr;
    cudaGetSymbolAddress((void**)&qkv, g_qkv);
    cudaGetSymbolAddress((void**)&att, g_att);

    // 1) qkv = x1 @ W_qkv  (4096x1024 @ 1024x2048), 3-pass tf32
    {
        dim3 grid(2 * CDIM / 128, SEQ / 128);
        tgemm3<false><<<grid, 256>>>(x1, W_qkv, nullptr, qkv, SEQ, 2 * CDIM, CDIM);
    }

    // 2) flash attention (tf32 mma)
    {
        int smem = (128 * 68 + 64 * 68 + 64 * 64) * (int)sizeof(float);
        cudaFuncSetAttribute(flash_mma,
                             cudaFuncAttributeMaxDynamicSharedMemorySize, smem);
        dim3 grid(SEQ / 128, NH);
        flash_mma<<<grid, 128, smem>>>(qkv, x2, att);
    }

    // 3) out = att @ W_proj + b_proj  (4096x1024 @ 1024x1024), 3-pass tf32
    {
        dim3 grid(CDIM / 128, SEQ / 128);
        tgemm3<true><<<grid, 256>>>(att, W_proj, b_proj, out, SEQ, CDIM, CDIM);
    }
}

// round 3
// speedup vs baseline: 2.9425x; 1.2563x over previous
#include <cuda_runtime.h>
#include <cuda_bf16.h>
#include <cstdint>

#define SEQ  4096
#define CDIM 1024
#define NH   16
#define HDIM 64

__device__ float g_qkv[SEQ * 2 * CDIM];
__device__ float g_att[SEQ * CDIM];

// ---------------------------------------------------------------------------
__device__ __forceinline__ uint32_t f2tf(float x) {
    uint32_t r;
    asm("cvt.rna.tf32.f32 %0, %1;" : "=r"(r) : "f"(x));
    return r;
}

__device__ __forceinline__ void mma_tf32(float* d, const uint32_t* a, const uint32_t* b) {
    asm volatile(
        "mma.sync.aligned.m16n8k8.row.col.f32.tf32.tf32.f32 "
        "{%0,%1,%2,%3}, {%4,%5,%6,%7}, {%8,%9}, {%0,%1,%2,%3};\n"
        : "+f"(d[0]), "+f"(d[1]), "+f"(d[2]), "+f"(d[3])
        : "r"(a[0]), "r"(a[1]), "r"(a[2]), "r"(a[3]), "r"(b[0]), "r"(b[1]));
}

__device__ __forceinline__ void mma_bf16(float* d, const uint32_t* a, const uint32_t* b) {
    asm volatile(
        "mma.sync.aligned.m16n8k16.row.col.f32.bf16.bf16.f32 "
        "{%0,%1,%2,%3}, {%4,%5,%6,%7}, {%8,%9}, {%0,%1,%2,%3};\n"
        : "+f"(d[0]), "+f"(d[1]), "+f"(d[2]), "+f"(d[3])
        : "r"(a[0]), "r"(a[1]), "r"(a[2]), "r"(a[3]), "r"(b[0]), "r"(b[1]));
}

__device__ __forceinline__ void cpasync16(void* smem_dst, const void* gsrc) {
    uint32_t s = (uint32_t)__cvta_generic_to_shared(smem_dst);
    asm volatile("cp.async.cg.shared.global [%0], [%1], 16;\n" :: "r"(s), "l"(gsrc));
}

__device__ __forceinline__ uint32_t pack_bf2(float x0, float x1) {
    __nv_bfloat162 h = __floats2bfloat162_rn(x0, x1);  // low = x0
    return *reinterpret_cast<uint32_t*>(&h);
}

// ---------------------------------------------------------------------------
// bf16 split GEMM: C = A @ B (+bias), near-fp32 accuracy (hi/lo split, 3 mma).
// 128x128 block, BK=16, 8 warps (2x4), warp tile 64x32, mma m16n8k16.
// A smem: pair-packed bf16 along k, XOR-swizzled (conflict-free LDS.64).
// B smem: pair-packed [k2][n] stride 136 (conflict-free).
// ---------------------------------------------------------------------------
template <bool HAS_BIAS>
__global__ void __launch_bounds__(256)
bgemm(const float* __restrict__ A, const float* __restrict__ B,
      const float* __restrict__ bias, float* __restrict__ C,
      int M, int N, int K)
{
    __shared__ uint32_t Ah[2][128 * 8], Al[2][128 * 8];
    __shared__ uint32_t Bh[2][8 * 136], Bl[2][8 * 136];

    int tid  = threadIdx.x;
    int lane = tid & 31, wid = tid >> 5;
    int g = lane >> 2, tig = lane & 3;
    int warpM = wid >> 2, warpN = wid & 3;
    int bm0 = blockIdx.y * 128, bn0 = blockIdx.x * 128;

    // loader mapping
    int ar = tid >> 1, ahalf = tid & 1;          // A: row, k-half (8 k each)
    int bk2 = tid >> 5, bn4 = (tid & 31) * 4;    // B: k-pair, 4 n

    float acc[4][4][4];
    #pragma unroll
    for (int a = 0; a < 4; a++)
        #pragma unroll
        for (int b = 0; b < 4; b++)
            #pragma unroll
            for (int c = 0; c < 4; c++) acc[a][b][c] = 0.f;

    const int NT = K / 16;

    float4 ra0, ra1, rb0, rb1;
    auto ldg_tile = [&](int k0) {
        const float* Ap = A + (size_t)(bm0 + ar) * K + k0 + ahalf * 8;
        ra0 = *(const float4*)(Ap);
        ra1 = *(const float4*)(Ap + 4);
        const float* Bp = B + (size_t)(k0 + 2 * bk2) * N + bn0 + bn4;
        rb0 = *(const float4*)(Bp);
        rb1 = *(const float4*)(Bp + N);
    };

    auto sts_tile = [&](int buf) {
        // A: 8 consecutive k -> 4 pairs, j = 0..3, slot = ahalf
        float av[8] = { ra0.x, ra0.y, ra0.z, ra0.w, ra1.x, ra1.y, ra1.z, ra1.w };
        #pragma unroll
        for (int p = 0; p < 4; p++) {
            float x0 = av[2 * p], x1 = av[2 * p + 1];
            float h0 = __bfloat162float(__float2bfloat16_rn(x0));
            float h1 = __bfloat162float(__float2bfloat16_rn(x1));
            int jp = (p ^ (ar & 3)) * 2 + ahalf;
            Ah[buf][ar * 8 + jp] = pack_bf2(h0, h1);
            Al[buf][ar * 8 + jp] = pack_bf2(x0 - h0, x1 - h1);
        }
        // B: pair rows 2*bk2, 2*bk2+1, 4 n
        float bv0[4] = { rb0.x, rb0.y, rb0.z, rb0.w };
        float bv1[4] = { rb1.x, rb1.y, rb1.z, rb1.w };
        #pragma unroll
        for (int q = 0; q < 4; q++) {
            float x0 = bv0[q], x1 = bv1[q];
            float h0 = __bfloat162float(__float2bfloat16_rn(x0));
            float h1 = __bfloat162float(__float2bfloat16_rn(x1));
            Bh[buf][bk2 * 136 + bn4 + q] = pack_bf2(h0, h1);
            Bl[buf][bk2 * 136 + bn4 + q] = pack_bf2(x0 - h0, x1 - h1);
        }
    };

    ldg_tile(0);
    sts_tile(0);
    __syncthreads();

    for (int kt = 0; kt < NT; kt++) {
        int cur = kt & 1;
        if (kt + 1 < NT) ldg_tile((kt + 1) * 16);

        const uint32_t* ah = Ah[cur];
        const uint32_t* al = Al[cur];
        const uint32_t* bh = Bh[cur];
        const uint32_t* bl = Bl[cur];

        // fragments
        uint2 fah[4][2], fal[4][2];
        int jj = (tig ^ (g & 3)) * 2;
        #pragma unroll
        for (int mt = 0; mt < 4; mt++) {
            int r0 = warpM * 64 + mt * 16 + g;
            fah[mt][0] = *(const uint2*)&ah[r0 * 8 + jj];
            fah[mt][1] = *(const uint2*)&ah[(r0 + 8) * 8 + jj];
            fal[mt][0] = *(const uint2*)&al[r0 * 8 + jj];
            fal[mt][1] = *(const uint2*)&al[(r0 + 8) * 8 + jj];
        }
        uint32_t fbh[4][2], fbl[4][2];
        #pragma unroll
        for (int nt = 0; nt < 4; nt++) {
            int col = warpN * 32 + nt * 8 + g;
            fbh[nt][0] = bh[tig * 136 + col];
            fbh[nt][1] = bh[(tig + 4) * 136 + col];
            fbl[nt][0] = bl[tig * 136 + col];
            fbl[nt][1] = bl[(tig + 4) * 136 + col];
        }

        #pragma unroll
        for (int mt = 0; mt < 4; mt++) {
            uint32_t a_hi[4] = { fah[mt][0].x, fah[mt][1].x, fah[mt][0].y, fah[mt][1].y };
            uint32_t a_lo[4] = { fal[mt][0].x, fal[mt][1].x, fal[mt][0].y, fal[mt][1].y };
            #pragma unroll
            for (int nt = 0; nt < 4; nt++) {
                mma_bf16(acc[mt][nt], a_lo, fbh[nt]);
                mma_bf16(acc[mt][nt], a_hi, fbl[nt]);
                mma_bf16(acc[mt][nt], a_hi, fbh[nt]);
            }
        }

        __syncthreads();
        if (kt + 1 < NT) {
            sts_tile(cur ^ 1);
            __syncthreads();
        }
    }

    #pragma unroll
    for (int mt = 0; mt < 4; mt++) {
        int row0 = bm0 + warpM * 64 + mt * 16 + g;
        #pragma unroll
        for (int nt = 0; nt < 4; nt++) {
            int col = bn0 + warpN * 32 + nt * 8 + 2 * tig;
            float b0 = 0.f, b1 = 0.f;
            if (HAS_BIAS) { b0 = bias[col]; b1 = bias[col + 1]; }
            float2 v0 = { acc[mt][nt][0] + b0, acc[mt][nt][1] + b1 };
            float2 v1 = { acc[mt][nt][2] + b0, acc[mt][nt][3] + b1 };
            *(float2*)(C + (size_t)row0 * N + col) = v0;
            *(float2*)(C + (size_t)(row0 + 8) * N + col) = v1;
        }
    }
}

// ---------------------------------------------------------------------------
// Flash attention, tf32 mma. 4 warps, 128 Q rows, 64-key tiles.
// Q pre-converted to tf32 in smem (no cvt in loop); K/V cp.async
// double-buffered raw fp32 (cvt at fragment load).
// ---------------------------------------------------------------------------
__global__ void __launch_bounds__(128)
flash_mma(const float* __restrict__ qkv, const float* __restrict__ x2,
          float* __restrict__ outb)
{
    extern __shared__ float sm[];
    uint32_t* Qu = (uint32_t*)sm;              // 128 x 68 tf32 bits
    float* Kraw = sm + 128 * 68;               // 2 x 64 x 68
    float* Vraw = Kraw + 2 * 64 * 68;          // 2 x 64 x 64 (xor swizzled)

    int tid  = threadIdx.x;
    int lane = tid & 31, wid = tid >> 5;
    int g = lane >> 2, tig = lane & 3;
    int h  = blockIdx.y;
    int q0 = blockIdx.x * 128;
    int wr = wid * 32;

    auto issue_kv = [&](int t, int buf) {
        int kv0 = t * 64;
        float* Kb = Kraw + buf * 64 * 68;
        float* Vb = Vraw + buf * 64 * 64;
        #pragma unroll
        for (int i = 0; i < 8; i++) {
            int idx = i * 128 + tid;
            int r = idx >> 4, c4 = (idx & 15) * 4;
            cpasync16(&Kb[r * 68 + c4],
                      qkv + (size_t)(kv0 + r) * 2048 + 1024 + h * 64 + c4);
            cpasync16(&Vb[r * 64 + (c4 ^ ((r & 7) << 3))],
                      x2 + (size_t)(kv0 + r) * 1024 + h * 64 + c4);
        }
        asm volatile("cp.async.commit_group;\n");
    };

    issue_kv(0, 0);

    // load Q (scaled, tf32-converted)
    #pragma unroll
    for (int i = 0; i < 16; i++) {
        int idx = i * 128 + tid;
        int r = idx >> 4, c4 = (idx & 15) * 4;
        float4 v = *(const float4*)(qkv + (size_t)(q0 + r) * 2048 + h * 64 + c4);
        uint32_t* p = &Qu[r * 68 + c4];
        p[0] = f2tf(v.x * 0.125f); p[1] = f2tf(v.y * 0.125f);
        p[2] = f2tf(v.z * 0.125f); p[3] = f2tf(v.w * 0.125f);
    }

    float m_i[4], l_i[4], accO[2][8][4];
    #pragma unroll
    for (int i = 0; i < 4; i++) { m_i[i] = -1e30f; l_i[i] = 0.f; }
    #pragma unroll
    for (int mt = 0; mt < 2; mt++)
        #pragma unroll
        for (int dn = 0; dn < 8; dn++)
            #pragma unroll
            for (int c = 0; c < 4; c++) accO[mt][dn][c] = 0.f;

    const int src0 = tig >> 1;
    const bool odd = tig & 1;

    for (int t = 0; t < SEQ / 64; t++) {
        int cur = t & 1;
        if (t + 1 < SEQ / 64) {
            issue_kv(t + 1, cur ^ 1);
            asm volatile("cp.async.wait_group 1;\n");
        } else {
            asm volatile("cp.async.wait_group 0;\n");
        }
        __syncthreads();   // tile t visible to all; also guards Q on t=0

        const float* Kb = Kraw + cur * 64 * 68;
        const float* Vb = Vraw + cur * 64 * 64;

        // ---- S = Q @ K^T ----
        float s[2][8][4];
        #pragma unroll
        for (int mt = 0; mt < 2; mt++)
            #pragma unroll
            for (int nt = 0; nt < 8; nt++)
                #pragma unroll
                for (int c = 0; c < 4; c++) s[mt][nt][c] = 0.f;

        #pragma unroll
        for (int kc = 0; kc < 8; kc++) {
            uint32_t qa[2][4];
            #pragma unroll
            for (int mt = 0; mt < 2; mt++) {
                int rb = wr + mt * 16;
                qa[mt][0] = Qu[(rb + g)     * 68 + kc * 8 + tig];
                qa[mt][1] = Qu[(rb + 8 + g) * 68 + kc * 8 + tig];
                qa[mt][2] = Qu[(rb + g)     * 68 + kc * 8 + tig + 4];
                qa[mt][3] = Qu[(rb + 8 + g) * 68 + kc * 8 + tig + 4];
            }
            #pragma unroll
            for (int nt = 0; nt < 8; nt++) {
                uint32_t kb[2];
                kb[0] = f2tf(Kb[(nt * 8 + g) * 68 + kc * 8 + tig]);
                kb[1] = f2tf(Kb[(nt * 8 + g) * 68 + kc * 8 + tig + 4]);
                mma_tf32(s[0][nt], qa[0], kb);
                mma_tf32(s[1][nt], qa[1], kb);
            }
        }

        // ---- online softmax ----
        #pragma unroll
        for (int mt = 0; mt < 2; mt++)
            #pragma unroll
            for (int rg = 0; rg < 2; rg++) {
                int ri = mt * 2 + rg;
                float mx = -1e30f;
                #pragma unroll
                for (int nt = 0; nt < 8; nt++) {
                    mx = fmaxf(mx, s[mt][nt][2 * rg]);
                    mx = fmaxf(mx, s[mt][nt][2 * rg + 1]);
                }
                mx = fmaxf(mx, __shfl_xor_sync(0xffffffffu, mx, 1));
                mx = fmaxf(mx, __shfl_xor_sync(0xffffffffu, mx, 2));
                float mnew = fmaxf(m_i[ri], mx);
                float corr = __expf(m_i[ri] - mnew);
                m_i[ri] = mnew;
                float rs = 0.f;
                #pragma unroll
                for (int nt = 0; nt < 8; nt++) {
                    float p0 = __expf(s[mt][nt][2 * rg]     - mnew);
                    float p1 = __expf(s[mt][nt][2 * rg + 1] - mnew);
                    s[mt][nt][2 * rg]     = p0;
                    s[mt][nt][2 * rg + 1] = p1;
                    rs += p0 + p1;
                }
                rs += __shfl_xor_sync(0xffffffffu, rs, 1);
                rs += __shfl_xor_sync(0xffffffffu, rs, 2);
                l_i[ri] = l_i[ri] * corr + rs;
                #pragma unroll
                for (int dn = 0; dn < 8; dn++) {
                    accO[mt][dn][2 * rg]     *= corr;
                    accO[mt][dn][2 * rg + 1] *= corr;
                }
            }

        // ---- O += P @ V (in-register C->A transpose via shuffles) ----
        #pragma unroll
        for (int kc = 0; kc < 8; kc++) {
            uint32_t pa[2][4];
            #pragma unroll
            for (int mt = 0; mt < 2; mt++) {
                float s0 = s[mt][kc][0], s1 = s[mt][kc][1];
                float s2 = s[mt][kc][2], s3 = s[mt][kc][3];
                float v00 = __shfl_sync(0xffffffffu, s0, src0, 4);
                float v10 = __shfl_sync(0xffffffffu, s1, src0, 4);
                float v20 = __shfl_sync(0xffffffffu, s2, src0, 4);
                float v30 = __shfl_sync(0xffffffffu, s3, src0, 4);
                float v01 = __shfl_sync(0xffffffffu, s0, src0 + 2, 4);
                float v11 = __shfl_sync(0xffffffffu, s1, src0 + 2, 4);
                float v21 = __shfl_sync(0xffffffffu, s2, src0 + 2, 4);
                float v31 = __shfl_sync(0xffffffffu, s3, src0 + 2, 4);
                pa[mt][0] = f2tf(odd ? v10 : v00);
                pa[mt][1] = f2tf(odd ? v30 : v20);
                pa[mt][2] = f2tf(odd ? v11 : v01);
                pa[mt][3] = f2tf(odd ? v31 : v21);
            }
            #pragma unroll
            for (int dn = 0; dn < 8; dn++) {
                uint32_t vb[2];
                int r0 = kc * 8 + tig, r1 = kc * 8 + tig + 4;
                vb[0] = f2tf(Vb[r0 * 64 + ((dn * 8 + g) ^ ((r0 & 7) << 3))]);
                vb[1] = f2tf(Vb[r1 * 64 + ((dn * 8 + g) ^ ((r1 & 7) << 3))]);
                mma_tf32(accO[0][dn], pa[0], vb);
                mma_tf32(accO[1][dn], pa[1], vb);
            }
        }
        __syncthreads();   // tile t fully consumed before buffer reuse
    }

    // ---- epilogue ----
    #pragma unroll
    for (int mt = 0; mt < 2; mt++)
        #pragma unroll
        for (int rg = 0; rg < 2; rg++) {
            int ri = mt * 2 + rg;
            float inv = 1.0f / l_i[ri];
            int r = q0 + wr + mt * 16 + g + rg * 8;
            #pragma unroll
            for (int dn = 0; dn < 8; dn++) {
                int col = h * 64 + dn * 8 + 2 * tig;
                float2 o = { accO[mt][dn][2 * rg] * inv,
                             accO[mt][dn][2 * rg + 1] * inv };
                *(float2*)(outb + (size_t)r * CDIM + col) = o;
            }
        }
}

// ---------------------------------------------------------------------------
extern "C" void kernel_launch(void* const* d_in, const int* in_sizes, int n_in,
                              void* d_out, int out_size)
{
    const float* x1     = (const float*)d_in[0];
    const float* x2     = (const float*)d_in[1];
    const float* W_qkv  = (const float*)d_in[2];
    const float* W_proj = (const float*)d_in[3];
    const float* b_proj = (const float*)d_in[4];
    float* out = (float*)d_out;

    float* qkv = nullptr;
    float* att = nullptr;
    cudaGetSymbolAddress((void**)&qkv, g_qkv);
    cudaGetSymbolAddress((void**)&att, g_att);

    {
        dim3 grid(2 * CDIM / 128, SEQ / 128);
        bgemm<false><<<grid, 256>>>(x1, W_qkv, nullptr, qkv, SEQ, 2 * CDIM, CDIM);
    }
    {
        int smem = (128 * 68 + 2 * 64 * 68 + 2 * 64 * 64) * (int)sizeof(float);
        cudaFuncSetAttribute(flash_mma,
                             cudaFuncAttributeMaxDynamicSharedMemorySize, smem);
        dim3 grid(SEQ / 128, NH);
        flash_mma<<<grid, 128, smem>>>(qkv, x2, att);
    }
    {
        dim3 grid(CDIM / 128, SEQ / 128);
        bgemm<true><<<grid, 256>>>(att, W_proj, b_proj, out, SEQ, CDIM, CDIM);
    }
}

// round 5
// speedup vs baseline: 3.6011x; 1.2238x over previous
#include <cuda_runtime.h>
#include <cuda_bf16.h>
#include <cstdint>

#define SEQ  4096
#define CDIM 1024
#define NH   16

// ---------------- scratch (allocation-free rule) ----------------
__device__ uint32_t      g_qkvu[SEQ * 2 * CDIM];     // tf32 bits: q(scaled), k
__device__ uint32_t      g_vu [SEQ * CDIM];          // V tf32 bits
__device__ __nv_bfloat16 g_x1h[SEQ * CDIM], g_x1l[SEQ * CDIM];
__device__ __nv_bfloat16 g_ath[SEQ * CDIM], g_atl[SEQ * CDIM];
__device__ __nv_bfloat16 g_wqh[2 * CDIM * CDIM], g_wql[2 * CDIM * CDIM];
__device__ __nv_bfloat16 g_wph[CDIM * CDIM],     g_wpl[CDIM * CDIM];

// ---------------- helpers ----------------
__device__ __forceinline__ uint32_t f2tf(float x) {
    uint32_t r;
    asm("cvt.rna.tf32.f32 %0, %1;" : "=r"(r) : "f"(x));
    return r;
}
__device__ __forceinline__ void mma_tf32(float* d, const uint32_t* a, const uint32_t* b) {
    asm volatile(
        "mma.sync.aligned.m16n8k8.row.col.f32.tf32.tf32.f32 "
        "{%0,%1,%2,%3}, {%4,%5,%6,%7}, {%8,%9}, {%0,%1,%2,%3};\n"
        : "+f"(d[0]), "+f"(d[1]), "+f"(d[2]), "+f"(d[3])
        : "r"(a[0]), "r"(a[1]), "r"(a[2]), "r"(a[3]), "r"(b[0]), "r"(b[1]));
}
__device__ __forceinline__ void mma_bf16(float* d, const uint32_t* a, const uint32_t* b) {
    asm volatile(
        "mma.sync.aligned.m16n8k16.row.col.f32.bf16.bf16.f32 "
        "{%0,%1,%2,%3}, {%4,%5,%6,%7}, {%8,%9}, {%0,%1,%2,%3};\n"
        : "+f"(d[0]), "+f"(d[1]), "+f"(d[2]), "+f"(d[3])
        : "r"(a[0]), "r"(a[1]), "r"(a[2]), "r"(a[3]), "r"(b[0]), "r"(b[1]));
}
__device__ __forceinline__ void cpasync16(void* smem_dst, const void* gsrc) {
    uint32_t s = (uint32_t)__cvta_generic_to_shared(smem_dst);
    asm volatile("cp.async.cg.shared.global [%0], [%1], 16;\n" :: "r"(s), "l"(gsrc));
}
__device__ __forceinline__ void ldsm_x4(uint32_t saddr, uint32_t* r) {
    asm volatile("ldmatrix.sync.aligned.m8n8.x4.shared.b16 {%0,%1,%2,%3}, [%4];"
        : "=r"(r[0]), "=r"(r[1]), "=r"(r[2]), "=r"(r[3]) : "r"(saddr));
}
__device__ __forceinline__ void ldsm_x4_t(uint32_t saddr, uint32_t* r) {
    asm volatile("ldmatrix.sync.aligned.m8n8.x4.trans.shared.b16 {%0,%1,%2,%3}, [%4];"
        : "=r"(r[0]), "=r"(r[1]), "=r"(r[2]), "=r"(r[3]) : "r"(saddr));
}

// ---------------- prep kernels ----------------
__global__ void split_pair(const float* __restrict__ s,
                           __nv_bfloat16* __restrict__ hi,
                           __nv_bfloat16* __restrict__ lo, int n)
{
    int i = (blockIdx.x * blockDim.x + threadIdx.x) * 4;
    if (i >= n) return;
    float4 v = *(const float4*)(s + i);
    __nv_bfloat162 h01 = __floats2bfloat162_rn(v.x, v.y);
    __nv_bfloat162 h23 = __floats2bfloat162_rn(v.z, v.w);
    *(__nv_bfloat162*)(hi + i)     = h01;
    *(__nv_bfloat162*)(hi + i + 2) = h23;
    __nv_bfloat162 l01 = __floats2bfloat162_rn(v.x - __bfloat162float(h01.x),
                                               v.y - __bfloat162float(h01.y));
    __nv_bfloat162 l23 = __floats2bfloat162_rn(v.z - __bfloat162float(h23.x),
                                               v.w - __bfloat162float(h23.y));
    *(__nv_bfloat162*)(lo + i)     = l01;
    *(__nv_bfloat162*)(lo + i + 2) = l23;
}

__global__ void cvt_tf(const float* __restrict__ s, uint32_t* __restrict__ d, int n)
{
    int i = (blockIdx.x * blockDim.x + threadIdx.x) * 4;
    if (i >= n) return;
    float4 v = *(const float4*)(s + i);
    uint4 o = { f2tf(v.x), f2tf(v.y), f2tf(v.z), f2tf(v.w) };
    *(uint4*)(d + i) = o;
}

// ---------------------------------------------------------------------------
// bf16 hi/lo split GEMM from pre-split operands. 128x128x16 tiles, 8 warps,
// warp 64x32, cp.async double buffer, ldmatrix frags, 3 mma per k16.
// EPI 0: write u32 tf32 bits (scale 0.125 for cols < CDIM). EPI 1: f32+bias.
// ---------------------------------------------------------------------------
template <int EPI>
__global__ void __launch_bounds__(256)
bgemm(const __nv_bfloat16* __restrict__ Ah_, const __nv_bfloat16* __restrict__ Al_,
      const __nv_bfloat16* __restrict__ Bh_, const __nv_bfloat16* __restrict__ Bl_,
      const float* __restrict__ bias, void* __restrict__ Cout,
      int M, int N, int K)
{
    __shared__ __nv_bfloat16 sAh[2][128 * 16], sAl[2][128 * 16];
    __shared__ __nv_bfloat16 sBh[2][16 * 128], sBl[2][16 * 128];

    int tid  = threadIdx.x;
    int lane = tid & 31, wid = tid >> 5;
    int g = lane >> 2, tig = lane & 3;
    int warpM = wid >> 2, warpN = wid & 3;
    int bm0 = blockIdx.y * 128, bn0 = blockIdx.x * 128;

    float acc[4][4][4];
    #pragma unroll
    for (int a = 0; a < 4; a++)
        #pragma unroll
        for (int b = 0; b < 4; b++)
            #pragma unroll
            for (int c = 0; c < 4; c++) acc[a][b][c] = 0.f;

    const int NT = K / 16;

    int am = tid >> 1, akc = tid & 1;
    int aoff = am * 32 + 16 * (akc ^ ((am >> 2) & 1));
    int bk = tid >> 4, bnc = tid & 15;
    int boff = bk * 256 + 16 * (bnc ^ (bk & 7));

    auto issue = [&](int kt, int buf) {
        int k0 = kt * 16;
        size_t asrc = (size_t)(bm0 + am) * K + k0 + akc * 8;
        cpasync16((char*)sAh[buf] + aoff, Ah_ + asrc);
        cpasync16((char*)sAl[buf] + aoff, Al_ + asrc);
        size_t bsrc = (size_t)(k0 + bk) * N + bn0 + bnc * 8;
        cpasync16((char*)sBh[buf] + boff, Bh_ + bsrc);
        cpasync16((char*)sBl[buf] + boff, Bl_ + bsrc);
        asm volatile("cp.async.commit_group;\n");
    };

    int a_m  = ((lane >> 3) & 1) * 8 + (lane & 7);
    int a_kc = lane >> 4;
    int b_k  = ((lane >> 3) & 1) * 8 + (lane & 7);
    int b_n8 = lane >> 4;

    issue(0, 0);

    for (int kt = 0; kt < NT; kt++) {
        int cur = kt & 1;
        if (kt + 1 < NT) {
            issue(kt + 1, cur ^ 1);
            asm volatile("cp.async.wait_group 1;\n");
        } else {
            asm volatile("cp.async.wait_group 0;\n");
        }
        __syncthreads();

        uint32_t fah[4][4], fal[4][4];
        #pragma unroll
        for (int mt = 0; mt < 4; mt++) {
            int m = warpM * 64 + mt * 16 + a_m;
            int off = m * 32 + 16 * (a_kc ^ ((m >> 2) & 1));
            ldsm_x4((uint32_t)__cvta_generic_to_shared((char*)sAh[cur] + off), fah[mt]);
            ldsm_x4((uint32_t)__cvta_generic_to_shared((char*)sAl[cur] + off), fal[mt]);
        }
        uint32_t fbh[2][4], fbl[2][4];
        #pragma unroll
        for (int p = 0; p < 2; p++) {
            int n = warpN * 32 + p * 16 + b_n8 * 8;
            int off = b_k * 256 + 16 * ((n >> 3) ^ (b_k & 7));
            ldsm_x4_t((uint32_t)__cvta_generic_to_shared((char*)sBh[cur] + off), fbh[p]);
            ldsm_x4_t((uint32_t)__cvta_generic_to_shared((char*)sBl[cur] + off), fbl[p]);
        }
        __syncthreads();

        #pragma unroll
        for (int mt = 0; mt < 4; mt++)
            #pragma unroll
            for (int nt = 0; nt < 4; nt++) {
                int p = nt >> 1, s2 = (nt & 1) * 2;
                uint32_t bh[2] = { fbh[p][s2], fbh[p][s2 + 1] };
                uint32_t bl[2] = { fbl[p][s2], fbl[p][s2 + 1] };
                mma_bf16(acc[mt][nt], fal[mt], bh);
                mma_bf16(acc[mt][nt], fah[mt], bl);
                mma_bf16(acc[mt][nt], fah[mt], bh);
            }
    }

    if (EPI == 0) {
        uint32_t* C = (uint32_t*)Cout;
        float scale = (bn0 < CDIM) ? 0.125f : 1.0f;
        #pragma unroll
        for (int mt = 0; mt < 4; mt++) {
            int row0 = bm0 + warpM * 64 + mt * 16 + g;
            #pragma unroll
            for (int nt = 0; nt < 4; nt++) {
                int col = bn0 + warpN * 32 + nt * 8 + 2 * tig;
                uint2 v0 = { f2tf(acc[mt][nt][0] * scale), f2tf(acc[mt][nt][1] * scale) };
                uint2 v1 = { f2tf(acc[mt][nt][2] * scale), f2tf(acc[mt][nt][3] * scale) };
                *(uint2*)(C + (size_t)row0 * N + col) = v0;
                *(uint2*)(C + (size_t)(row0 + 8) * N + col) = v1;
            }
        }
    } else {
        float* C = (float*)Cout;
        #pragma unroll
        for (int mt = 0; mt < 4; mt++) {
            int row0 = bm0 + warpM * 64 + mt * 16 + g;
            #pragma unroll
            for (int nt = 0; nt < 4; nt++) {
                int col = bn0 + warpN * 32 + nt * 8 + 2 * tig;
                float b0 = bias[col], b1 = bias[col + 1];
                float2 v0 = { acc[mt][nt][0] + b0, acc[mt][nt][1] + b1 };
                float2 v1 = { acc[mt][nt][2] + b0, acc[mt][nt][3] + b1 };
                *(float2*)(C + (size_t)row0 * N + col) = v0;
                *(float2*)(C + (size_t)(row0 + 8) * N + col) = v1;
            }
        }
    }
}

// ---------------------------------------------------------------------------
// Flash attention. Q/K/V all tf32 bits pre-made (zero cvt in the S and V
// load paths). S: tf32 mma. PV: tf32 mma with in-register C->A transpose
// (shuffles) + cvt.rna on P. Output written as bf16 hi/lo for bgemm<1>.
// ---------------------------------------------------------------------------
__global__ void __launch_bounds__(128)
flash_mma(const uint32_t* __restrict__ qkv, const uint32_t* __restrict__ vsrc,
          __nv_bfloat16* __restrict__ outh, __nv_bfloat16* __restrict__ outl)
{
    extern __shared__ uint32_t smu[];
    uint32_t* Qu  = smu;                      // 128 x 68
    uint32_t* Kb0 = Qu + 128 * 68;            // 2 x 64 x 68
    uint32_t* Vb0 = Kb0 + 2 * 64 * 68;        // 2 x 64 x 64 (xor swizzled)

    int tid  = threadIdx.x;
    int lane = tid & 31, wid = tid >> 5;
    int g = lane >> 2, tig = lane & 3;
    int h  = blockIdx.y;
    int q0 = blockIdx.x * 128;
    int wr = wid * 32;

    auto issue_kv = [&](int t, int buf) {
        int kv0 = t * 64;
        uint32_t* Kb = Kb0 + buf * 64 * 68;
        uint32_t* Vb = Vb0 + buf * 64 * 64;
        #pragma unroll
        for (int i = 0; i < 8; i++) {
            int idx = i * 128 + tid;
            int r = idx >> 4, c4 = (idx & 15) * 4;
            cpasync16(Kb + r * 68 + c4,
                      qkv + (size_t)(kv0 + r) * 2048 + 1024 + h * 64 + c4);
            cpasync16(Vb + r * 64 + (c4 ^ ((r & 7) << 3)),
                      vsrc + (size_t)(kv0 + r) * 1024 + h * 64 + c4);
        }
        asm volatile("cp.async.commit_group;\n");
    };

    issue_kv(0, 0);
    #pragma unroll
    for (int i = 0; i < 16; i++) {
        int idx = i * 128 + tid;
        int r = idx >> 4, c4 = (idx & 15) * 4;
        cpasync16(Qu + r * 68 + c4, qkv + (size_t)(q0 + r) * 2048 + h * 64 + c4);
    }
    asm volatile("cp.async.commit_group;\n");

    float m_i[4], l_i[4], accO[2][8][4];
    #pragma unroll
    for (int i = 0; i < 4; i++) { m_i[i] = -1e30f; l_i[i] = 0.f; }
    #pragma unroll
    for (int mt = 0; mt < 2; mt++)
        #pragma unroll
        for (int dn = 0; dn < 8; dn++)
            #pragma unroll
            for (int c = 0; c < 4; c++) accO[mt][dn][c] = 0.f;

    const int src0 = tig >> 1;
    const bool odd = tig & 1;

    for (int t = 0; t < SEQ / 64; t++) {
        int cur = t & 1;
        if (t + 1 < SEQ / 64) {
            issue_kv(t + 1, cur ^ 1);
            asm volatile("cp.async.wait_group 1;\n");
        } else {
            asm volatile("cp.async.wait_group 0;\n");
        }
        __syncthreads();

        const uint32_t* Kb = Kb0 + cur * 64 * 68;
        const uint32_t* Vb = Vb0 + cur * 64 * 64;

        // ---- S = Q @ K^T (tf32, zero cvt) ----
        float s[2][8][4];
        #pragma unroll
        for (int mt = 0; mt < 2; mt++)
            #pragma unroll
            for (int nt = 0; nt < 8; nt++)
                #pragma unroll
                for (int c = 0; c < 4; c++) s[mt][nt][c] = 0.f;

        #pragma unroll
        for (int kc = 0; kc < 8; kc++) {
            uint32_t qa[2][4];
            #pragma unroll
            for (int mt = 0; mt < 2; mt++) {
                int rb = wr + mt * 16;
                qa[mt][0] = Qu[(rb + g)     * 68 + kc * 8 + tig];
                qa[mt][1] = Qu[(rb + 8 + g) * 68 + kc * 8 + tig];
                qa[mt][2] = Qu[(rb + g)     * 68 + kc * 8 + tig + 4];
                qa[mt][3] = Qu[(rb + 8 + g) * 68 + kc * 8 + tig + 4];
            }
            #pragma unroll
            for (int nt = 0; nt < 8; nt++) {
                uint32_t kb[2];
                kb[0] = Kb[(nt * 8 + g) * 68 + kc * 8 + tig];
                kb[1] = Kb[(nt * 8 + g) * 68 + kc * 8 + tig + 4];
                mma_tf32(s[0][nt], qa[0], kb);
                mma_tf32(s[1][nt], qa[1], kb);
            }
        }

        // ---- online softmax ----
        #pragma unroll
        for (int mt = 0; mt < 2; mt++)
            #pragma unroll
            for (int rg = 0; rg < 2; rg++) {
                int ri = mt * 2 + rg;
                float mx = -1e30f;
                #pragma unroll
                for (int nt = 0; nt < 8; nt++) {
                    mx = fmaxf(mx, s[mt][nt][2 * rg]);
                    mx = fmaxf(mx, s[mt][nt][2 * rg + 1]);
                }
                mx = fmaxf(mx, __shfl_xor_sync(0xffffffffu, mx, 1));
                mx = fmaxf(mx, __shfl_xor_sync(0xffffffffu, mx, 2));
                float mnew = fmaxf(m_i[ri], mx);
                float corr = __expf(m_i[ri] - mnew);
                m_i[ri] = mnew;
                float rs = 0.f;
                #pragma unroll
                for (int nt = 0; nt < 8; nt++) {
                    float p0 = __expf(s[mt][nt][2 * rg]     - mnew);
                    float p1 = __expf(s[mt][nt][2 * rg + 1] - mnew);
                    s[mt][nt][2 * rg]     = p0;
                    s[mt][nt][2 * rg + 1] = p1;
                    rs += p0 + p1;
                }
                rs += __shfl_xor_sync(0xffffffffu, rs, 1);
                rs += __shfl_xor_sync(0xffffffffu, rs, 2);
                l_i[ri] = l_i[ri] * corr + rs;
                #pragma unroll
                for (int dn = 0; dn < 8; dn++) {
                    accO[mt][dn][2 * rg]     *= corr;
                    accO[mt][dn][2 * rg + 1] *= corr;
                }
            }

        // ---- O += P @ V (tf32; C->A transpose via width-4 shuffles) ----
        #pragma unroll
        for (int kc = 0; kc < 8; kc++) {
            uint32_t pa[2][4];
            #pragma unroll
            for (int mt = 0; mt < 2; mt++) {
                float s0 = s[mt][kc][0], s1 = s[mt][kc][1];
                float s2 = s[mt][kc][2], s3 = s[mt][kc][3];
                float v00 = __shfl_sync(0xffffffffu, s0, src0, 4);
                float v10 = __shfl_sync(0xffffffffu, s1, src0, 4);
                float v20 = __shfl_sync(0xffffffffu, s2, src0, 4);
                float v30 = __shfl_sync(0xffffffffu, s3, src0, 4);
                float v01 = __shfl_sync(0xffffffffu, s0, src0 + 2, 4);
                float v11 = __shfl_sync(0xffffffffu, s1, src0 + 2, 4);
                float v21 = __shfl_sync(0xffffffffu, s2, src0 + 2, 4);
                float v31 = __shfl_sync(0xffffffffu, s3, src0 + 2, 4);
                pa[mt][0] = f2tf(odd ? v10 : v00);
                pa[mt][1] = f2tf(odd ? v30 : v20);
                pa[mt][2] = f2tf(odd ? v11 : v01);
                pa[mt][3] = f2tf(odd ? v31 : v21);
            }
            #pragma unroll
            for (int dn = 0; dn < 8; dn++) {
                uint32_t vb[2];
                int r0 = kc * 8 + tig, r1 = kc * 8 + tig + 4;
                vb[0] = Vb[r0 * 64 + ((dn * 8 + g) ^ ((r0 & 7) << 3))];
                vb[1] = Vb[r1 * 64 + ((dn * 8 + g) ^ ((r1 & 7) << 3))];
                mma_tf32(accO[0][dn], pa[0], vb);
                mma_tf32(accO[1][dn], pa[1], vb);
            }
        }
        __syncthreads();
    }

    // ---- epilogue: write att as bf16 hi/lo ----
    #pragma unroll
    for (int mt = 0; mt < 2; mt++)
        #pragma unroll
        for (int rg = 0; rg < 2; rg++) {
            int ri = mt * 2 + rg;
            float inv = 1.0f / l_i[ri];
            int r = q0 + wr + mt * 16 + g + rg * 8;
            #pragma unroll
            for (int dn = 0; dn < 8; dn++) {
                int col = h * 64 + dn * 8 + 2 * tig;
                float o0 = accO[mt][dn][2 * rg] * inv;
                float o1 = accO[mt][dn][2 * rg + 1] * inv;
                __nv_bfloat162 hi = __floats2bfloat162_rn(o0, o1);
                __nv_bfloat162 lo = __floats2bfloat162_rn(o0 - __bfloat162float(hi.x),
                                                          o1 - __bfloat162float(hi.y));
                *(__nv_bfloat162*)(outh + (size_t)r * CDIM + col) = hi;
                *(__nv_bfloat162*)(outl + (size_t)r * CDIM + col) = lo;
            }
        }
}

// ---------------------------------------------------------------------------
extern "C" void kernel_launch(void* const* d_in, const int* in_sizes, int n_in,
                              void* d_out, int out_size)
{
    const float* x1     = (const float*)d_in[0];
    const float* x2     = (const float*)d_in[1];
    const float* W_qkv  = (const float*)d_in[2];
    const float* W_proj = (const float*)d_in[3];
    const float* b_proj = (const float*)d_in[4];
    float* out = (float*)d_out;

    uint32_t *qkvu, *vu;
    __nv_bfloat16 *x1h, *x1l, *ath, *atl, *wqh, *wql, *wph, *wpl;
    cudaGetSymbolAddress((void**)&qkvu, g_qkvu);
    cudaGetSymbolAddress((void**)&vu,  g_vu);
    cudaGetSymbolAddress((void**)&x1h, g_x1h);
    cudaGetSymbolAddress((void**)&x1l, g_x1l);
    cudaGetSymbolAddress((void**)&ath, g_ath);
    cudaGetSymbolAddress((void**)&atl, g_atl);
    cudaGetSymbolAddress((void**)&wqh, g_wqh);
    cudaGetSymbolAddress((void**)&wql, g_wql);
    cudaGetSymbolAddress((void**)&wph, g_wph);
    cudaGetSymbolAddress((void**)&wpl, g_wpl);

    split_pair<<<SEQ * CDIM / 1024, 256>>>(x1, x1h, x1l, SEQ * CDIM);
    split_pair<<<2 * CDIM * CDIM / 1024, 256>>>(W_qkv, wqh, wql, 2 * CDIM * CDIM);
    split_pair<<<CDIM * CDIM / 1024, 256>>>(W_proj, wph, wpl, CDIM * CDIM);
    cvt_tf<<<SEQ * CDIM / 1024, 256>>>(x2, vu, SEQ * CDIM);

    {
        dim3 grid(2 * CDIM / 128, SEQ / 128);
        bgemm<0><<<grid, 256>>>(x1h, x1l, wqh, wql, nullptr, qkvu,
                                SEQ, 2 * CDIM, CDIM);
    }
    {
        int smem = (128 * 68 + 2 * 64 * 68 + 2 * 64 * 64) * 4;
        cudaFuncSetAttribute(flash_mma,
                             cudaFuncAttributeMaxDynamicSharedMemorySize, smem);
        dim3 grid(SEQ / 128, NH);
        flash_mma<<<grid, 128, smem>>>(qkvu, vu, ath, atl);
    }
    {
        dim3 grid(CDIM / 128, SEQ / 128);
        bgemm<1><<<grid, 256>>>(ath, atl, wph, wpl, b_proj, out,
                                SEQ, CDIM, CDIM);
    }
}

// round 6
// speedup vs baseline: 3.9003x; 1.0831x over previous
#include <cuda_runtime.h>
#include <cuda_bf16.h>
#include <cuda_fp16.h>
#include <cstdint>

#define SEQ  4096
#define CDIM 1024
#define NH   16

// ---------------- scratch (allocation-free rule) ----------------
__device__ uint32_t      g_qkvu[SEQ * 2 * CDIM];     // tf32 bits: q(scaled), k
__device__ __half        g_vh [SEQ * CDIM];          // V fp16
__device__ __nv_bfloat16 g_x1h[SEQ * CDIM], g_x1l[SEQ * CDIM];
__device__ __nv_bfloat16 g_ath[SEQ * CDIM], g_atl[SEQ * CDIM];
__device__ __nv_bfloat16 g_wqh[2 * CDIM * CDIM], g_wql[2 * CDIM * CDIM];
__device__ __nv_bfloat16 g_wph[CDIM * CDIM],     g_wpl[CDIM * CDIM];

// ---------------- helpers ----------------
__device__ __forceinline__ uint32_t f2tf(float x) {
    uint32_t r;
    asm("cvt.rna.tf32.f32 %0, %1;" : "=r"(r) : "f"(x));
    return r;
}
__device__ __forceinline__ void mma_tf32(float* d, const uint32_t* a, const uint32_t* b) {
    asm volatile(
        "mma.sync.aligned.m16n8k8.row.col.f32.tf32.tf32.f32 "
        "{%0,%1,%2,%3}, {%4,%5,%6,%7}, {%8,%9}, {%0,%1,%2,%3};\n"
        : "+f"(d[0]), "+f"(d[1]), "+f"(d[2]), "+f"(d[3])
        : "r"(a[0]), "r"(a[1]), "r"(a[2]), "r"(a[3]), "r"(b[0]), "r"(b[1]));
}
__device__ __forceinline__ void mma_bf16(float* d, const uint32_t* a, const uint32_t* b) {
    asm volatile(
        "mma.sync.aligned.m16n8k16.row.col.f32.bf16.bf16.f32 "
        "{%0,%1,%2,%3}, {%4,%5,%6,%7}, {%8,%9}, {%0,%1,%2,%3};\n"
        : "+f"(d[0]), "+f"(d[1]), "+f"(d[2]), "+f"(d[3])
        : "r"(a[0]), "r"(a[1]), "r"(a[2]), "r"(a[3]), "r"(b[0]), "r"(b[1]));
}
__device__ __forceinline__ void mma_f16(float* d, const uint32_t* a, const uint32_t* b) {
    asm volatile(
        "mma.sync.aligned.m16n8k16.row.col.f32.f16.f16.f32 "
        "{%0,%1,%2,%3}, {%4,%5,%6,%7}, {%8,%9}, {%0,%1,%2,%3};\n"
        : "+f"(d[0]), "+f"(d[1]), "+f"(d[2]), "+f"(d[3])
        : "r"(a[0]), "r"(a[1]), "r"(a[2]), "r"(a[3]), "r"(b[0]), "r"(b[1]));
}
__device__ __forceinline__ void cpasync16(void* smem_dst, const void* gsrc) {
    uint32_t s = (uint32_t)__cvta_generic_to_shared(smem_dst);
    asm volatile("cp.async.cg.shared.global [%0], [%1], 16;\n" :: "r"(s), "l"(gsrc));
}
__device__ __forceinline__ void ldsm_x4(uint32_t saddr, uint32_t* r) {
    asm volatile("ldmatrix.sync.aligned.m8n8.x4.shared.b16 {%0,%1,%2,%3}, [%4];"
        : "=r"(r[0]), "=r"(r[1]), "=r"(r[2]), "=r"(r[3]) : "r"(saddr));
}
__device__ __forceinline__ void ldsm_x4_t(uint32_t saddr, uint32_t* r) {
    asm volatile("ldmatrix.sync.aligned.m8n8.x4.trans.shared.b16 {%0,%1,%2,%3}, [%4];"
        : "=r"(r[0]), "=r"(r[1]), "=r"(r[2]), "=r"(r[3]) : "r"(saddr));
}
__device__ __forceinline__ uint32_t packh2(float lo, float hi) {
    __half2 h = __floats2half2_rn(lo, hi);  // .x = lo
    return *reinterpret_cast<uint32_t*>(&h);
}

// ---------------- prep kernels ----------------
__global__ void split_pair(const float* __restrict__ s,
                           __nv_bfloat16* __restrict__ hi,
                           __nv_bfloat16* __restrict__ lo, int n)
{
    int i = (blockIdx.x * blockDim.x + threadIdx.x) * 4;
    if (i >= n) return;
    float4 v = *(const float4*)(s + i);
    __nv_bfloat162 h01 = __floats2bfloat162_rn(v.x, v.y);
    __nv_bfloat162 h23 = __floats2bfloat162_rn(v.z, v.w);
    *(__nv_bfloat162*)(hi + i)     = h01;
    *(__nv_bfloat162*)(hi + i + 2) = h23;
    __nv_bfloat162 l01 = __floats2bfloat162_rn(v.x - __bfloat162float(h01.x),
                                               v.y - __bfloat162float(h01.y));
    __nv_bfloat162 l23 = __floats2bfloat162_rn(v.z - __bfloat162float(h23.x),
                                               v.w - __bfloat162float(h23.y));
    *(__nv_bfloat162*)(lo + i)     = l01;
    *(__nv_bfloat162*)(lo + i + 2) = l23;
}

__global__ void cvt_f16(const float* __restrict__ s, __half* __restrict__ d, int n)
{
    int i = (blockIdx.x * blockDim.x + threadIdx.x) * 4;
    if (i >= n) return;
    float4 v = *(const float4*)(s + i);
    *(__half2*)(d + i)     = __floats2half2_rn(v.x, v.y);
    *(__half2*)(d + i + 2) = __floats2half2_rn(v.z, v.w);
}

// ---------------------------------------------------------------------------
// bf16 hi/lo split GEMM from pre-split operands. 128x128x16 tiles, 8 warps,
// warp 64x32, cp.async double buffer, ldmatrix frags, 3 mma per k16.
// EPI 0: write u32 tf32 bits (scale 0.125 for cols < CDIM). EPI 1: f32+bias.
// ---------------------------------------------------------------------------
template <int EPI>
__global__ void __launch_bounds__(256)
bgemm(const __nv_bfloat16* __restrict__ Ah_, const __nv_bfloat16* __restrict__ Al_,
      const __nv_bfloat16* __restrict__ Bh_, const __nv_bfloat16* __restrict__ Bl_,
      const float* __restrict__ bias, void* __restrict__ Cout,
      int M, int N, int K)
{
    __shared__ __nv_bfloat16 sAh[2][128 * 16], sAl[2][128 * 16];
    __shared__ __nv_bfloat16 sBh[2][16 * 128], sBl[2][16 * 128];

    int tid  = threadIdx.x;
    int lane = tid & 31, wid = tid >> 5;
    int g = lane >> 2, tig = lane & 3;
    int warpM = wid >> 2, warpN = wid & 3;
    int bm0 = blockIdx.y * 128, bn0 = blockIdx.x * 128;

    float acc[4][4][4];
    #pragma unroll
    for (int a = 0; a < 4; a++)
        #pragma unroll
        for (int b = 0; b < 4; b++)
            #pragma unroll
            for (int c = 0; c < 4; c++) acc[a][b][c] = 0.f;

    const int NT = K / 16;

    int am = tid >> 1, akc = tid & 1;
    int aoff = am * 32 + 16 * (akc ^ ((am >> 2) & 1));
    int bk = tid >> 4, bnc = tid & 15;
    int boff = bk * 256 + 16 * (bnc ^ (bk & 7));

    auto issue = [&](int kt, int buf) {
        int k0 = kt * 16;
        size_t asrc = (size_t)(bm0 + am) * K + k0 + akc * 8;
        cpasync16((char*)sAh[buf] + aoff, Ah_ + asrc);
        cpasync16((char*)sAl[buf] + aoff, Al_ + asrc);
        size_t bsrc = (size_t)(k0 + bk) * N + bn0 + bnc * 8;
        cpasync16((char*)sBh[buf] + boff, Bh_ + bsrc);
        cpasync16((char*)sBl[buf] + boff, Bl_ + bsrc);
        asm volatile("cp.async.commit_group;\n");
    };

    int a_m  = ((lane >> 3) & 1) * 8 + (lane & 7);
    int a_kc = lane >> 4;
    int b_k  = ((lane >> 3) & 1) * 8 + (lane & 7);
    int b_n8 = lane >> 4;

    issue(0, 0);

    for (int kt = 0; kt < NT; kt++) {
        int cur = kt & 1;
        if (kt + 1 < NT) {
            issue(kt + 1, cur ^ 1);
            asm volatile("cp.async.wait_group 1;\n");
        } else {
            asm volatile("cp.async.wait_group 0;\n");
        }
        __syncthreads();

        uint32_t fah[4][4], fal[4][4];
        #pragma unroll
        for (int mt = 0; mt < 4; mt++) {
            int m = warpM * 64 + mt * 16 + a_m;
            int off = m * 32 + 16 * (a_kc ^ ((m >> 2) & 1));
            ldsm_x4((uint32_t)__cvta_generic_to_shared((char*)sAh[cur] + off), fah[mt]);
            ldsm_x4((uint32_t)__cvta_generic_to_shared((char*)sAl[cur] + off), fal[mt]);
        }
        uint32_t fbh[2][4], fbl[2][4];
        #pragma unroll
        for (int p = 0; p < 2; p++) {
            int n = warpN * 32 + p * 16 + b_n8 * 8;
            int off = b_k * 256 + 16 * ((n >> 3) ^ (b_k & 7));
            ldsm_x4_t((uint32_t)__cvta_generic_to_shared((char*)sBh[cur] + off), fbh[p]);
            ldsm_x4_t((uint32_t)__cvta_generic_to_shared((char*)sBl[cur] + off), fbl[p]);
        }
        __syncthreads();

        #pragma unroll
        for (int mt = 0; mt < 4; mt++)
            #pragma unroll
            for (int nt = 0; nt < 4; nt++) {
                int p = nt >> 1, s2 = (nt & 1) * 2;
                uint32_t bh[2] = { fbh[p][s2], fbh[p][s2 + 1] };
                uint32_t bl[2] = { fbl[p][s2], fbl[p][s2 + 1] };
                mma_bf16(acc[mt][nt], fal[mt], bh);
                mma_bf16(acc[mt][nt], fah[mt], bl);
                mma_bf16(acc[mt][nt], fah[mt], bh);
            }
    }

    if (EPI == 0) {
        uint32_t* C = (uint32_t*)Cout;
        float scale = (bn0 < CDIM) ? 0.125f : 1.0f;
        #pragma unroll
        for (int mt = 0; mt < 4; mt++) {
            int row0 = bm0 + warpM * 64 + mt * 16 + g;
            #pragma unroll
            for (int nt = 0; nt < 4; nt++) {
                int col = bn0 + warpN * 32 + nt * 8 + 2 * tig;
                uint2 v0 = { f2tf(acc[mt][nt][0] * scale), f2tf(acc[mt][nt][1] * scale) };
                uint2 v1 = { f2tf(acc[mt][nt][2] * scale), f2tf(acc[mt][nt][3] * scale) };
                *(uint2*)(C + (size_t)row0 * N + col) = v0;
                *(uint2*)(C + (size_t)(row0 + 8) * N + col) = v1;
            }
        }
    } else {
        float* C = (float*)Cout;
        #pragma unroll
        for (int mt = 0; mt < 4; mt++) {
            int row0 = bm0 + warpM * 64 + mt * 16 + g;
            #pragma unroll
            for (int nt = 0; nt < 4; nt++) {
                int col = bn0 + warpN * 32 + nt * 8 + 2 * tig;
                float b0 = bias[col], b1 = bias[col + 1];
                float2 v0 = { acc[mt][nt][0] + b0, acc[mt][nt][1] + b1 };
                float2 v1 = { acc[mt][nt][2] + b0, acc[mt][nt][3] + b1 };
                *(float2*)(C + (size_t)row0 * N + col) = v0;
                *(float2*)(C + (size_t)(row0 + 8) * N + col) = v1;
            }
        }
    }
}

// ---------------------------------------------------------------------------
// Flash attention. S: tf32 mma (Q/K tf32 bits pre-made, zero cvt).
// PV: fp16 mma — P repacked directly from S C-frags (no shuffles),
// V fp16 via swizzled ldmatrix.x4.trans. Output bf16 hi/lo for bgemm<1>.
// ---------------------------------------------------------------------------
__global__ void __launch_bounds__(128)
flash_mma(const uint32_t* __restrict__ qkv, const __half* __restrict__ vsrc,
          __nv_bfloat16* __restrict__ outh, __nv_bfloat16* __restrict__ outl)
{
    extern __shared__ uint32_t smu[];
    uint32_t* Qu  = smu;                      // 128 x 68 tf32
    uint32_t* Kb0 = Qu + 128 * 68;            // 2 x 64 x 68 tf32
    char* Vb0 = (char*)(Kb0 + 2 * 64 * 68);   // 2 x 64 x 128B fp16 (swizzled)

    int tid  = threadIdx.x;
    int lane = tid & 31, wid = tid >> 5;
    int g = lane >> 2, tig = lane & 3;
    int h  = blockIdx.y;
    int q0 = blockIdx.x * 128;
    int wr = wid * 32;

    auto issue_kv = [&](int t, int buf) {
        int kv0 = t * 64;
        uint32_t* Kb = Kb0 + buf * 64 * 68;
        char* Vb = Vb0 + buf * 64 * 128;
        #pragma unroll
        for (int i = 0; i < 8; i++) {
            int idx = i * 128 + tid;
            int r = idx >> 4, c4 = (idx & 15) * 4;
            cpasync16(Kb + r * 68 + c4,
                      qkv + (size_t)(kv0 + r) * 2048 + 1024 + h * 64 + c4);
        }
        #pragma unroll
        for (int i = 0; i < 4; i++) {
            int idx = i * 128 + tid;
            int r = idx >> 3, c8 = (idx & 7) * 8;   // 8 fp16 = 16B
            cpasync16(Vb + r * 128 + 16 * ((c8 >> 3) ^ (r & 7)),
                      vsrc + (size_t)(kv0 + r) * 1024 + h * 64 + c8);
        }
        asm volatile("cp.async.commit_group;\n");
    };

    issue_kv(0, 0);
    #pragma unroll
    for (int i = 0; i < 16; i++) {
        int idx = i * 128 + tid;
        int r = idx >> 4, c4 = (idx & 15) * 4;
        cpasync16(Qu + r * 68 + c4, qkv + (size_t)(q0 + r) * 2048 + h * 64 + c4);
    }
    asm volatile("cp.async.commit_group;\n");

    float m_i[4], l_i[4], accO[2][8][4];
    #pragma unroll
    for (int i = 0; i < 4; i++) { m_i[i] = -1e30f; l_i[i] = 0.f; }
    #pragma unroll
    for (int mt = 0; mt < 2; mt++)
        #pragma unroll
        for (int dn = 0; dn < 8; dn++)
            #pragma unroll
            for (int c = 0; c < 4; c++) accO[mt][dn][c] = 0.f;

    // V ldmatrix lane mapping
    int v_r8 = ((lane >> 3) & 1) * 8 + (lane & 7);
    int v_d8 = (lane >> 4) * 8;

    for (int t = 0; t < SEQ / 64; t++) {
        int cur = t & 1;
        if (t + 1 < SEQ / 64) {
            issue_kv(t + 1, cur ^ 1);
            asm volatile("cp.async.wait_group 1;\n");
        } else {
            asm volatile("cp.async.wait_group 0;\n");
        }
        __syncthreads();

        const uint32_t* Kb = Kb0 + cur * 64 * 68;
        char* Vb = Vb0 + cur * 64 * 128;

        // ---- S = Q @ K^T (tf32, zero cvt) ----
        float s[2][8][4];
        #pragma unroll
        for (int mt = 0; mt < 2; mt++)
            #pragma unroll
            for (int nt = 0; nt < 8; nt++)
                #pragma unroll
                for (int c = 0; c < 4; c++) s[mt][nt][c] = 0.f;

        #pragma unroll
        for (int kc = 0; kc < 8; kc++) {
            uint32_t qa[2][4];
            #pragma unroll
            for (int mt = 0; mt < 2; mt++) {
                int rb = wr + mt * 16;
                qa[mt][0] = Qu[(rb + g)     * 68 + kc * 8 + tig];
                qa[mt][1] = Qu[(rb + 8 + g) * 68 + kc * 8 + tig];
                qa[mt][2] = Qu[(rb + g)     * 68 + kc * 8 + tig + 4];
                qa[mt][3] = Qu[(rb + 8 + g) * 68 + kc * 8 + tig + 4];
            }
            #pragma unroll
            for (int nt = 0; nt < 8; nt++) {
                uint32_t kb[2];
                kb[0] = Kb[(nt * 8 + g) * 68 + kc * 8 + tig];
                kb[1] = Kb[(nt * 8 + g) * 68 + kc * 8 + tig + 4];
                mma_tf32(s[0][nt], qa[0], kb);
                mma_tf32(s[1][nt], qa[1], kb);
            }
        }

        // ---- online softmax ----
        #pragma unroll
        for (int mt = 0; mt < 2; mt++)
            #pragma unroll
            for (int rg = 0; rg < 2; rg++) {
                int ri = mt * 2 + rg;
                float mx = -1e30f;
                #pragma unroll
                for (int nt = 0; nt < 8; nt++) {
                    mx = fmaxf(mx, s[mt][nt][2 * rg]);
                    mx = fmaxf(mx, s[mt][nt][2 * rg + 1]);
                }
                mx = fmaxf(mx, __shfl_xor_sync(0xffffffffu, mx, 1));
                mx = fmaxf(mx, __shfl_xor_sync(0xffffffffu, mx, 2));
                float mnew = fmaxf(m_i[ri], mx);
                float corr = __expf(m_i[ri] - mnew);
                m_i[ri] = mnew;
                float rs = 0.f;
                #pragma unroll
                for (int nt = 0; nt < 8; nt++) {
                    float p0 = __expf(s[mt][nt][2 * rg]     - mnew);
                    float p1 = __expf(s[mt][nt][2 * rg + 1] - mnew);
                    s[mt][nt][2 * rg]     = p0;
                    s[mt][nt][2 * rg + 1] = p1;
                    rs += p0 + p1;
                }
                rs += __shfl_xor_sync(0xffffffffu, rs, 1);
                rs += __shfl_xor_sync(0xffffffffu, rs, 2);
                l_i[ri] = l_i[ri] * corr + rs;
                #pragma unroll
                for (int dn = 0; dn < 8; dn++) {
                    accO[mt][dn][2 * rg]     *= corr;
                    accO[mt][dn][2 * rg + 1] *= corr;
                }
            }

        // ---- O += P @ V (fp16 k16; P = repacked C-frags, no shuffles) ----
        #pragma unroll
        for (int kc = 0; kc < 4; kc++) {
            uint32_t pa[2][4];
            #pragma unroll
            for (int mt = 0; mt < 2; mt++) {
                pa[mt][0] = packh2(s[mt][2 * kc][0],     s[mt][2 * kc][1]);
                pa[mt][1] = packh2(s[mt][2 * kc][2],     s[mt][2 * kc][3]);
                pa[mt][2] = packh2(s[mt][2 * kc + 1][0], s[mt][2 * kc + 1][1]);
                pa[mt][3] = packh2(s[mt][2 * kc + 1][2], s[mt][2 * kc + 1][3]);
            }
            #pragma unroll
            for (int dnp = 0; dnp < 4; dnp++) {
                int key = kc * 16 + v_r8;
                int d   = dnp * 16 + v_d8;
                uint32_t vb4[4];
                uint32_t addr = (uint32_t)__cvta_generic_to_shared(
                    Vb + key * 128 + 16 * ((d >> 3) ^ (key & 7)));
                ldsm_x4_t(addr, vb4);
                uint32_t vlo[2] = { vb4[0], vb4[1] };
                uint32_t vhi[2] = { vb4[2], vb4[3] };
                mma_f16(accO[0][2 * dnp],     pa[0], vlo);
                mma_f16(accO[0][2 * dnp + 1], pa[0], vhi);
                mma_f16(accO[1][2 * dnp],     pa[1], vlo);
                mma_f16(accO[1][2 * dnp + 1], pa[1], vhi);
            }
        }
        __syncthreads();
    }

    // ---- epilogue: write att as bf16 hi/lo ----
    #pragma unroll
    for (int mt = 0; mt < 2; mt++)
        #pragma unroll
        for (int rg = 0; rg < 2; rg++) {
            int ri = mt * 2 + rg;
            float inv = 1.0f / l_i[ri];
            int r = q0 + wr + mt * 16 + g + rg * 8;
            #pragma unroll
            for (int dn = 0; dn < 8; dn++) {
                int col = h * 64 + dn * 8 + 2 * tig;
                float o0 = accO[mt][dn][2 * rg] * inv;
                float o1 = accO[mt][dn][2 * rg + 1] * inv;
                __nv_bfloat162 hi = __floats2bfloat162_rn(o0, o1);
                __nv_bfloat162 lo = __floats2bfloat162_rn(o0 - __bfloat162float(hi.x),
                                                          o1 - __bfloat162float(hi.y));
                *(__nv_bfloat162*)(outh + (size_t)r * CDIM + col) = hi;
                *(__nv_bfloat162*)(outl + (size_t)r * CDIM + col) = lo;
            }
        }
}

// ---------------------------------------------------------------------------
extern "C" void kernel_launch(void* const* d_in, const int* in_sizes, int n_in,
                              void* d_out, int out_size)
{
    const float* x1     = (const float*)d_in[0];
    const float* x2     = (const float*)d_in[1];
    const float* W_qkv  = (const float*)d_in[2];
    const float* W_proj = (const float*)d_in[3];
    const float* b_proj = (const float*)d_in[4];
    float* out = (float*)d_out;

    uint32_t* qkvu; __half* vh;
    __nv_bfloat16 *x1h, *x1l, *ath, *atl, *wqh, *wql, *wph, *wpl;
    cudaGetSymbolAddress((void**)&qkvu, g_qkvu);
    cudaGetSymbolAddress((void**)&vh,  g_vh);
    cudaGetSymbolAddress((void**)&x1h, g_x1h);
    cudaGetSymbolAddress((void**)&x1l, g_x1l);
    cudaGetSymbolAddress((void**)&ath, g_ath);
    cudaGetSymbolAddress((void**)&atl, g_atl);
    cudaGetSymbolAddress((void**)&wqh, g_wqh);
    cudaGetSymbolAddress((void**)&wql, g_wql);
    cudaGetSymbolAddress((void**)&wph, g_wph);
    cudaGetSymbolAddress((void**)&wpl, g_wpl);

    split_pair<<<SEQ * CDIM / 1024, 256>>>(x1, x1h, x1l, SEQ * CDIM);
    split_pair<<<2 * CDIM * CDIM / 1024, 256>>>(W_qkv, wqh, wql, 2 * CDIM * CDIM);
    split_pair<<<CDIM * CDIM / 1024, 256>>>(W_proj, wph, wpl, CDIM * CDIM);
    cvt_f16<<<SEQ * CDIM / 1024, 256>>>(x2, vh, SEQ * CDIM);

    {
        dim3 grid(2 * CDIM / 128, SEQ / 128);
        bgemm<0><<<grid, 256>>>(x1h, x1l, wqh, wql, nullptr, qkvu,
                                SEQ, 2 * CDIM, CDIM);
    }
    {
        int smem = (128 * 68 + 2 * 64 * 68) * 4 + 2 * 64 * 128;
        cudaFuncSetAttribute(flash_mma,
                             cudaFuncAttributeMaxDynamicSharedMemorySize, smem);
        dim3 grid(SEQ / 128, NH);
        flash_mma<<<grid, 128, smem>>>(qkvu, vh, ath, atl);
    }
    {
        dim3 grid(CDIM / 128, SEQ / 128);
        bgemm<1><<<grid, 256>>>(ath, atl, wph, wpl, b_proj, out,
                                SEQ, CDIM, CDIM);
    }
}

// round 7
// speedup vs baseline: 5.2829x; 1.3545x over previous
#include <cuda_runtime.h>
#include <cuda_bf16.h>
#include <cuda_fp16.h>
#include <cstdint>

#define SEQ  4096
#define CDIM 1024
#define NH   16

// ---------------- scratch (allocation-free rule) ----------------
__device__ __half        g_qkvh[SEQ * 2 * CDIM];     // fp16: q(scaled by 0.125*log2e), k
__device__ __half        g_vh [SEQ * CDIM];          // V fp16
__device__ __nv_bfloat16 g_x1h[SEQ * CDIM], g_x1l[SEQ * CDIM];
__device__ __nv_bfloat16 g_ath[SEQ * CDIM], g_atl[SEQ * CDIM];
__device__ __nv_bfloat16 g_wqh[2 * CDIM * CDIM], g_wql[2 * CDIM * CDIM];
__device__ __nv_bfloat16 g_wph[CDIM * CDIM],     g_wpl[CDIM * CDIM];

// ---------------- helpers ----------------
__device__ __forceinline__ void mma_bf16(float* d, const uint32_t* a, const uint32_t* b) {
    asm volatile(
        "mma.sync.aligned.m16n8k16.row.col.f32.bf16.bf16.f32 "
        "{%0,%1,%2,%3}, {%4,%5,%6,%7}, {%8,%9}, {%0,%1,%2,%3};\n"
        : "+f"(d[0]), "+f"(d[1]), "+f"(d[2]), "+f"(d[3])
        : "r"(a[0]), "r"(a[1]), "r"(a[2]), "r"(a[3]), "r"(b[0]), "r"(b[1]));
}
__device__ __forceinline__ void mma_f16(float* d, const uint32_t* a, const uint32_t* b) {
    asm volatile(
        "mma.sync.aligned.m16n8k16.row.col.f32.f16.f16.f32 "
        "{%0,%1,%2,%3}, {%4,%5,%6,%7}, {%8,%9}, {%0,%1,%2,%3};\n"
        : "+f"(d[0]), "+f"(d[1]), "+f"(d[2]), "+f"(d[3])
        : "r"(a[0]), "r"(a[1]), "r"(a[2]), "r"(a[3]), "r"(b[0]), "r"(b[1]));
}
__device__ __forceinline__ void cpasync16(void* smem_dst, const void* gsrc) {
    uint32_t s = (uint32_t)__cvta_generic_to_shared(smem_dst);
    asm volatile("cp.async.cg.shared.global [%0], [%1], 16;\n" :: "r"(s), "l"(gsrc));
}
__device__ __forceinline__ void ldsm_x4(uint32_t saddr, uint32_t* r) {
    asm volatile("ldmatrix.sync.aligned.m8n8.x4.shared.b16 {%0,%1,%2,%3}, [%4];"
        : "=r"(r[0]), "=r"(r[1]), "=r"(r[2]), "=r"(r[3]) : "r"(saddr));
}
__device__ __forceinline__ void ldsm_x4_t(uint32_t saddr, uint32_t* r) {
    asm volatile("ldmatrix.sync.aligned.m8n8.x4.trans.shared.b16 {%0,%1,%2,%3}, [%4];"
        : "=r"(r[0]), "=r"(r[1]), "=r"(r[2]), "=r"(r[3]) : "r"(saddr));
}
__device__ __forceinline__ uint32_t packh2(float lo, float hi) {
    __half2 h = __floats2half2_rn(lo, hi);
    return *reinterpret_cast<uint32_t*>(&h);
}

// ---------------- prep kernels ----------------
__global__ void split_pair(const float* __restrict__ s,
                           __nv_bfloat16* __restrict__ hi,
                           __nv_bfloat16* __restrict__ lo, int n)
{
    int i = (blockIdx.x * blockDim.x + threadIdx.x) * 4;
    if (i >= n) return;
    float4 v = *(const float4*)(s + i);
    __nv_bfloat162 h01 = __floats2bfloat162_rn(v.x, v.y);
    __nv_bfloat162 h23 = __floats2bfloat162_rn(v.z, v.w);
    *(__nv_bfloat162*)(hi + i)     = h01;
    *(__nv_bfloat162*)(hi + i + 2) = h23;
    __nv_bfloat162 l01 = __floats2bfloat162_rn(v.x - __bfloat162float(h01.x),
                                               v.y - __bfloat162float(h01.y));
    __nv_bfloat162 l23 = __floats2bfloat162_rn(v.z - __bfloat162float(h23.x),
                                               v.w - __bfloat162float(h23.y));
    *(__nv_bfloat162*)(lo + i)     = l01;
    *(__nv_bfloat162*)(lo + i + 2) = l23;
}

__global__ void cvt_f16(const float* __restrict__ s, __half* __restrict__ d, int n)
{
    int i = (blockIdx.x * blockDim.x + threadIdx.x) * 4;
    if (i >= n) return;
    float4 v = *(const float4*)(s + i);
    *(__half2*)(d + i)     = __floats2half2_rn(v.x, v.y);
    *(__half2*)(d + i + 2) = __floats2half2_rn(v.z, v.w);
}

// ---------------------------------------------------------------------------
// bf16 hi/lo split GEMM. 128x128x16, 8 warps, ldmatrix, 3 mma per k16.
// EPI 0: write fp16 (q cols scaled by 0.125*log2e). EPI 1: f32 + bias.
// ---------------------------------------------------------------------------
template <int EPI>
__global__ void __launch_bounds__(256)
bgemm(const __nv_bfloat16* __restrict__ Ah_, const __nv_bfloat16* __restrict__ Al_,
      const __nv_bfloat16* __restrict__ Bh_, const __nv_bfloat16* __restrict__ Bl_,
      const float* __restrict__ bias, void* __restrict__ Cout,
      int M, int N, int K)
{
    __shared__ __nv_bfloat16 sAh[2][128 * 16], sAl[2][128 * 16];
    __shared__ __nv_bfloat16 sBh[2][16 * 128], sBl[2][16 * 128];

    int tid  = threadIdx.x;
    int lane = tid & 31, wid = tid >> 5;
    int g = lane >> 2, tig = lane & 3;
    int warpM = wid >> 2, warpN = wid & 3;
    int bm0 = blockIdx.y * 128, bn0 = blockIdx.x * 128;

    float acc[4][4][4];
    #pragma unroll
    for (int a = 0; a < 4; a++)
        #pragma unroll
        for (int b = 0; b < 4; b++)
            #pragma unroll
            for (int c = 0; c < 4; c++) acc[a][b][c] = 0.f;

    const int NT = K / 16;

    int am = tid >> 1, akc = tid & 1;
    int aoff = am * 32 + 16 * (akc ^ ((am >> 2) & 1));
    int bk = tid >> 4, bnc = tid & 15;
    int boff = bk * 256 + 16 * (bnc ^ (bk & 7));

    auto issue = [&](int kt, int buf) {
        int k0 = kt * 16;
        size_t asrc = (size_t)(bm0 + am) * K + k0 + akc * 8;
        cpasync16((char*)sAh[buf] + aoff, Ah_ + asrc);
        cpasync16((char*)sAl[buf] + aoff, Al_ + asrc);
        size_t bsrc = (size_t)(k0 + bk) * N + bn0 + bnc * 8;
        cpasync16((char*)sBh[buf] + boff, Bh_ + bsrc);
        cpasync16((char*)sBl[buf] + boff, Bl_ + bsrc);
        asm volatile("cp.async.commit_group;\n");
    };

    int a_m  = ((lane >> 3) & 1) * 8 + (lane & 7);
    int a_kc = lane >> 4;
    int b_k  = ((lane >> 3) & 1) * 8 + (lane & 7);
    int b_n8 = lane >> 4;

    issue(0, 0);

    for (int kt = 0; kt < NT; kt++) {
        int cur = kt & 1;
        if (kt + 1 < NT) {
            issue(kt + 1, cur ^ 1);
            asm volatile("cp.async.wait_group 1;\n");
        } else {
            asm volatile("cp.async.wait_group 0;\n");
        }
        __syncthreads();

        uint32_t fah[4][4], fal[4][4];
        #pragma unroll
        for (int mt = 0; mt < 4; mt++) {
            int m = warpM * 64 + mt * 16 + a_m;
            int off = m * 32 + 16 * (a_kc ^ ((m >> 2) & 1));
            ldsm_x4((uint32_t)__cvta_generic_to_shared((char*)sAh[cur] + off), fah[mt]);
            ldsm_x4((uint32_t)__cvta_generic_to_shared((char*)sAl[cur] + off), fal[mt]);
        }
        uint32_t fbh[2][4], fbl[2][4];
        #pragma unroll
        for (int p = 0; p < 2; p++) {
            int n = warpN * 32 + p * 16 + b_n8 * 8;
            int off = b_k * 256 + 16 * ((n >> 3) ^ (b_k & 7));
            ldsm_x4_t((uint32_t)__cvta_generic_to_shared((char*)sBh[cur] + off), fbh[p]);
            ldsm_x4_t((uint32_t)__cvta_generic_to_shared((char*)sBl[cur] + off), fbl[p]);
        }
        __syncthreads();

        #pragma unroll
        for (int mt = 0; mt < 4; mt++)
            #pragma unroll
            for (int nt = 0; nt < 4; nt++) {
                int p = nt >> 1, s2 = (nt & 1) * 2;
                uint32_t bh[2] = { fbh[p][s2], fbh[p][s2 + 1] };
                uint32_t bl[2] = { fbl[p][s2], fbl[p][s2 + 1] };
                mma_bf16(acc[mt][nt], fal[mt], bh);
                mma_bf16(acc[mt][nt], fah[mt], bl);
                mma_bf16(acc[mt][nt], fah[mt], bh);
            }
    }

    if (EPI == 0) {
        __half* C = (__half*)Cout;
        // q columns: fold softmax scale (1/8) and log2(e) for exp2-domain softmax
        float scale = (bn0 < CDIM) ? 0.18033688011112042f : 1.0f;
        #pragma unroll
        for (int mt = 0; mt < 4; mt++) {
            int row0 = bm0 + warpM * 64 + mt * 16 + g;
            #pragma unroll
            for (int nt = 0; nt < 4; nt++) {
                int col = bn0 + warpN * 32 + nt * 8 + 2 * tig;
                *(__half2*)(C + (size_t)row0 * N + col) =
                    __floats2half2_rn(acc[mt][nt][0] * scale, acc[mt][nt][1] * scale);
                *(__half2*)(C + (size_t)(row0 + 8) * N + col) =
                    __floats2half2_rn(acc[mt][nt][2] * scale, acc[mt][nt][3] * scale);
            }
        }
    } else {
        float* C = (float*)Cout;
        #pragma unroll
        for (int mt = 0; mt < 4; mt++) {
            int row0 = bm0 + warpM * 64 + mt * 16 + g;
            #pragma unroll
            for (int nt = 0; nt < 4; nt++) {
                int col = bn0 + warpN * 32 + nt * 8 + 2 * tig;
                float b0 = bias[col], b1 = bias[col + 1];
                float2 v0 = { acc[mt][nt][0] + b0, acc[mt][nt][1] + b1 };
                float2 v1 = { acc[mt][nt][2] + b0, acc[mt][nt][3] + b1 };
                *(float2*)(C + (size_t)row0 * N + col) = v0;
                *(float2*)(C + (size_t)(row0 + 8) * N + col) = v1;
            }
        }
    }
}

// ---------------------------------------------------------------------------
// Flash attention, all-fp16 operands (precision == tf32), fp32 accum.
// S: fp16 m16n8k16 with ldmatrix A/B frags. Softmax in exp2 domain
// (log2e folded into Q). PV: fp16 mma, P repacked from C-frags, V via
// swizzled ldmatrix.trans. Output bf16 hi/lo for bgemm<1>.
// ---------------------------------------------------------------------------
__global__ void __launch_bounds__(128)
flash_mma(const __half* __restrict__ qkv, const __half* __restrict__ vsrc,
          __nv_bfloat16* __restrict__ outh, __nv_bfloat16* __restrict__ outl)
{
    extern __shared__ char smc[];
    char* Qs  = smc;                  // 128 x 128B (fp16, swizzled)
    char* Kb0 = Qs + 128 * 128;       // 2 x 64 x 128B
    char* Vb0 = Kb0 + 2 * 64 * 128;   // 2 x 64 x 128B

    int tid  = threadIdx.x;
    int lane = tid & 31, wid = tid >> 5;
    int g = lane >> 2, tig = lane & 3;
    int h  = blockIdx.y;
    int q0 = blockIdx.x * 128;
    int wr = wid * 32;

    auto issue_kv = [&](int t, int buf) {
        int kv0 = t * 64;
        char* Kb = Kb0 + buf * 64 * 128;
        char* Vb = Vb0 + buf * 64 * 128;
        #pragma unroll
        for (int i = 0; i < 4; i++) {
            int idx = i * 128 + tid;
            int r = idx >> 3, c8 = (idx & 7) * 8;   // 8 fp16 = 16B
            int sw = 16 * ((c8 >> 3) ^ (r & 7));
            cpasync16(Kb + r * 128 + sw,
                      qkv + (size_t)(kv0 + r) * 2048 + 1024 + h * 64 + c8);
            cpasync16(Vb + r * 128 + sw,
                      vsrc + (size_t)(kv0 + r) * 1024 + h * 64 + c8);
        }
        asm volatile("cp.async.commit_group;\n");
    };

    issue_kv(0, 0);
    #pragma unroll
    for (int i = 0; i < 8; i++) {
        int idx = i * 128 + tid;
        int r = idx >> 3, c8 = (idx & 7) * 8;
        cpasync16(Qs + r * 128 + 16 * ((c8 >> 3) ^ (r & 7)),
                  qkv + (size_t)(q0 + r) * 2048 + h * 64 + c8);
    }
    asm volatile("cp.async.commit_group;\n");

    float m_i[4], l_i[4], accO[2][8][4];
    #pragma unroll
    for (int i = 0; i < 4; i++) { m_i[i] = -1e30f; l_i[i] = 0.f; }
    #pragma unroll
    for (int mt = 0; mt < 2; mt++)
        #pragma unroll
        for (int dn = 0; dn < 8; dn++)
            #pragma unroll
            for (int c = 0; c < 4; c++) accO[mt][dn][c] = 0.f;

    // ldmatrix lane mapping (shared by Q, K, V loads)
    int lm_row = ((lane >> 3) & 1) * 8 + (lane & 7);
    int lm_k8  = lane >> 4;          // 0/1 -> col chunk +0/+1

    for (int t = 0; t < SEQ / 64; t++) {
        int cur = t & 1;
        if (t + 1 < SEQ / 64) {
            issue_kv(t + 1, cur ^ 1);
            asm volatile("cp.async.wait_group 1;\n");
        } else {
            asm volatile("cp.async.wait_group 0;\n");
        }
        __syncthreads();

        char* Kb = Kb0 + cur * 64 * 128;
        char* Vb = Vb0 + cur * 64 * 128;

        // ---- S = Q @ K^T (fp16 k16, ldmatrix frags) ----
        float s[2][8][4];
        #pragma unroll
        for (int mt = 0; mt < 2; mt++)
            #pragma unroll
            for (int nt = 0; nt < 8; nt++)
                #pragma unroll
                for (int c = 0; c < 4; c++) s[mt][nt][c] = 0.f;

        #pragma unroll
        for (int kc = 0; kc < 4; kc++) {
            uint32_t qa[2][4];
            #pragma unroll
            for (int mt = 0; mt < 2; mt++) {
                int m = wr + mt * 16 + lm_row;
                uint32_t addr = (uint32_t)__cvta_generic_to_shared(
                    Qs + m * 128 + 16 * ((kc * 2 + lm_k8) ^ (m & 7)));
                ldsm_x4(addr, qa[mt]);
            }
            #pragma unroll
            for (int ntp = 0; ntp < 4; ntp++) {
                int n = ntp * 16 + lm_row;
                uint32_t kb4[4];
                uint32_t addr = (uint32_t)__cvta_generic_to_shared(
                    Kb + n * 128 + 16 * ((kc * 2 + lm_k8) ^ (n & 7)));
                ldsm_x4(addr, kb4);
                uint32_t be[2] = { kb4[0], kb4[2] };
                uint32_t bo[2] = { kb4[1], kb4[3] };
                mma_f16(s[0][2 * ntp],     qa[0], be);
                mma_f16(s[0][2 * ntp + 1], qa[0], bo);
                mma_f16(s[1][2 * ntp],     qa[1], be);
                mma_f16(s[1][2 * ntp + 1], qa[1], bo);
            }
        }

        // ---- online softmax (exp2 domain; log2e folded into Q) ----
        #pragma unroll
        for (int mt = 0; mt < 2; mt++)
            #pragma unroll
            for (int rg = 0; rg < 2; rg++) {
                int ri = mt * 2 + rg;
                float mx = -1e30f;
                #pragma unroll
                for (int nt = 0; nt < 8; nt++) {
                    mx = fmaxf(mx, s[mt][nt][2 * rg]);
                    mx = fmaxf(mx, s[mt][nt][2 * rg + 1]);
                }
                mx = fmaxf(mx, __shfl_xor_sync(0xffffffffu, mx, 1));
                mx = fmaxf(mx, __shfl_xor_sync(0xffffffffu, mx, 2));
                float mnew = fmaxf(m_i[ri], mx);
                float corr = exp2f(m_i[ri] - mnew);
                m_i[ri] = mnew;
                float rs = 0.f;
                #pragma unroll
                for (int nt = 0; nt < 8; nt++) {
                    float p0 = exp2f(s[mt][nt][2 * rg]     - mnew);
                    float p1 = exp2f(s[mt][nt][2 * rg + 1] - mnew);
                    s[mt][nt][2 * rg]     = p0;
                    s[mt][nt][2 * rg + 1] = p1;
                    rs += p0 + p1;
                }
                rs += __shfl_xor_sync(0xffffffffu, rs, 1);
                rs += __shfl_xor_sync(0xffffffffu, rs, 2);
                l_i[ri] = l_i[ri] * corr + rs;
                #pragma unroll
                for (int dn = 0; dn < 8; dn++) {
                    accO[mt][dn][2 * rg]     *= corr;
                    accO[mt][dn][2 * rg + 1] *= corr;
                }
            }

        // ---- O += P @ V (fp16 k16; P = repacked C-frags) ----
        #pragma unroll
        for (int kc = 0; kc < 4; kc++) {
            uint32_t pa[2][4];
            #pragma unroll
            for (int mt = 0; mt < 2; mt++) {
                pa[mt][0] = packh2(s[mt][2 * kc][0],     s[mt][2 * kc][1]);
                pa[mt][1] = packh2(s[mt][2 * kc][2],     s[mt][2 * kc][3]);
                pa[mt][2] = packh2(s[mt][2 * kc + 1][0], s[mt][2 * kc + 1][1]);
                pa[mt][3] = packh2(s[mt][2 * kc + 1][2], s[mt][2 * kc + 1][3]);
            }
            #pragma unroll
            for (int dnp = 0; dnp < 4; dnp++) {
                int key = kc * 16 + lm_row;
                int d   = dnp * 16 + lm_k8 * 8;
                uint32_t vb4[4];
                uint32_t addr = (uint32_t)__cvta_generic_to_shared(
                    Vb + key * 128 + 16 * ((d >> 3) ^ (key & 7)));
                ldsm_x4_t(addr, vb4);
                uint32_t vlo[2] = { vb4[0], vb4[1] };
                uint32_t vhi[2] = { vb4[2], vb4[3] };
                mma_f16(accO[0][2 * dnp],     pa[0], vlo);
                mma_f16(accO[0][2 * dnp + 1], pa[0], vhi);
                mma_f16(accO[1][2 * dnp],     pa[1], vlo);
                mma_f16(accO[1][2 * dnp + 1], pa[1], vhi);
            }
        }
        __syncthreads();
    }

    // ---- epilogue: write att as bf16 hi/lo ----
    #pragma unroll
    for (int mt = 0; mt < 2; mt++)
        #pragma unroll
        for (int rg = 0; rg < 2; rg++) {
            int ri = mt * 2 + rg;
            float inv = 1.0f / l_i[ri];
            int r = q0 + wr + mt * 16 + g + rg * 8;
            #pragma unroll
            for (int dn = 0; dn < 8; dn++) {
                int col = h * 64 + dn * 8 + 2 * tig;
                float o0 = accO[mt][dn][2 * rg] * inv;
                float o1 = accO[mt][dn][2 * rg + 1] * inv;
                __nv_bfloat162 hi = __floats2bfloat162_rn(o0, o1);
                __nv_bfloat162 lo = __floats2bfloat162_rn(o0 - __bfloat162float(hi.x),
                                                          o1 - __bfloat162float(hi.y));
                *(__nv_bfloat162*)(outh + (size_t)r * CDIM + col) = hi;
                *(__nv_bfloat162*)(outl + (size_t)r * CDIM + col) = lo;
            }
        }
}

// ---------------------------------------------------------------------------
extern "C" void kernel_launch(void* const* d_in, const int* in_sizes, int n_in,
                              void* d_out, int out_size)
{
    const float* x1     = (const float*)d_in[0];
    const float* x2     = (const float*)d_in[1];
    const float* W_qkv  = (const float*)d_in[2];
    const float* W_proj = (const float*)d_in[3];
    const float* b_proj = (const float*)d_in[4];
    float* out = (float*)d_out;

    __half *qkvh, *vh;
    __nv_bfloat16 *x1h, *x1l, *ath, *atl, *wqh, *wql, *wph, *wpl;
    cudaGetSymbolAddress((void**)&qkvh, g_qkvh);
    cudaGetSymbolAddress((void**)&vh,  g_vh);
    cudaGetSymbolAddress((void**)&x1h, g_x1h);
    cudaGetSymbolAddress((void**)&x1l, g_x1l);
    cudaGetSymbolAddress((void**)&ath, g_ath);
    cudaGetSymbolAddress((void**)&atl, g_atl);
    cudaGetSymbolAddress((void**)&wqh, g_wqh);
    cudaGetSymbolAddress((void**)&wql, g_wql);
    cudaGetSymbolAddress((void**)&wph, g_wph);
    cudaGetSymbolAddress((void**)&wpl, g_wpl);

    split_pair<<<SEQ * CDIM / 1024, 256>>>(x1, x1h, x1l, SEQ * CDIM);
    split_pair<<<2 * CDIM * CDIM / 1024, 256>>>(W_qkv, wqh, wql, 2 * CDIM * CDIM);
    split_pair<<<CDIM * CDIM / 1024, 256>>>(W_proj, wph, wpl, CDIM * CDIM);
    cvt_f16<<<SEQ * CDIM / 1024, 256>>>(x2, vh, SEQ * CDIM);

    {
        dim3 grid(2 * CDIM / 128, SEQ / 128);
        bgemm<0><<<grid, 256>>>(x1h, x1l, wqh, wql, nullptr, qkvh,
                                SEQ, 2 * CDIM, CDIM);
    }
    {
        int smem = 128 * 128 + 2 * 64 * 128 + 2 * 64 * 128;   // 48 KB
        cudaFuncSetAttribute(flash_mma,
                             cudaFuncAttributeMaxDynamicSharedMemorySize, smem);
        dim3 grid(SEQ / 128, NH);
        flash_mma<<<grid, 128, smem>>>(qkvh, vh, ath, atl);
    }
    {
        dim3 grid(CDIM / 128, SEQ / 128);
        bgemm<1><<<grid, 256>>>(ath, atl, wph, wpl, b_proj, out,
                                SEQ, CDIM, CDIM);
    }
}

// round 8
// speedup vs baseline: 7.4030x; 1.4013x over previous
#include <cuda_runtime.h>
#include <cuda_fp16.h>
#include <cstdint>

#define SEQ  4096
#define CDIM 1024
#define NH   16

// ---------------- scratch (allocation-free rule) ----------------
__device__ __half g_qkvh[SEQ * 2 * CDIM];   // fp16: q(scaled by 0.125*log2e), k
__device__ __half g_vh [SEQ * CDIM];        // V fp16
__device__ __half g_x1f[SEQ * CDIM];        // x1 fp16
__device__ __half g_atf[SEQ * CDIM];        // attention out fp16
__device__ __half g_wqf[2 * CDIM * CDIM];   // W_qkv fp16
__device__ __half g_wpf[CDIM * CDIM];       // W_proj fp16

// ---------------- helpers ----------------
__device__ __forceinline__ void mma_f16(float* d, const uint32_t* a, const uint32_t* b) {
    asm volatile(
        "mma.sync.aligned.m16n8k16.row.col.f32.f16.f16.f32 "
        "{%0,%1,%2,%3}, {%4,%5,%6,%7}, {%8,%9}, {%0,%1,%2,%3};\n"
        : "+f"(d[0]), "+f"(d[1]), "+f"(d[2]), "+f"(d[3])
        : "r"(a[0]), "r"(a[1]), "r"(a[2]), "r"(a[3]), "r"(b[0]), "r"(b[1]));
}
__device__ __forceinline__ void cpasync16(void* smem_dst, const void* gsrc) {
    uint32_t s = (uint32_t)__cvta_generic_to_shared(smem_dst);
    asm volatile("cp.async.cg.shared.global [%0], [%1], 16;\n" :: "r"(s), "l"(gsrc));
}
__device__ __forceinline__ void ldsm_x4(uint32_t saddr, uint32_t* r) {
    asm volatile("ldmatrix.sync.aligned.m8n8.x4.shared.b16 {%0,%1,%2,%3}, [%4];"
        : "=r"(r[0]), "=r"(r[1]), "=r"(r[2]), "=r"(r[3]) : "r"(saddr));
}
__device__ __forceinline__ void ldsm_x4_t(uint32_t saddr, uint32_t* r) {
    asm volatile("ldmatrix.sync.aligned.m8n8.x4.trans.shared.b16 {%0,%1,%2,%3}, [%4];"
        : "=r"(r[0]), "=r"(r[1]), "=r"(r[2]), "=r"(r[3]) : "r"(saddr));
}
__device__ __forceinline__ uint32_t packh2(float lo, float hi) {
    __half2 h = __floats2half2_rn(lo, hi);
    return *reinterpret_cast<uint32_t*>(&h);
}

// ---------------- prep: fp32 -> fp16 ----------------
__global__ void cvt_f16(const float* __restrict__ s, __half* __restrict__ d, int n)
{
    int i = (blockIdx.x * blockDim.x + threadIdx.x) * 4;
    if (i >= n) return;
    float4 v = *(const float4*)(s + i);
    *(__half2*)(d + i)     = __floats2half2_rn(v.x, v.y);
    *(__half2*)(d + i + 2) = __floats2half2_rn(v.z, v.w);
}

// ---------------------------------------------------------------------------
// Single-pass fp16 GEMM, fp32 accum. 128x128x16 tiles, 8 warps (2x4),
// warp tile 64x32, cp.async double buffer, swizzled ldmatrix frags.
// EPI 0: write fp16 (cols < CDIM scaled by 0.125*log2e). EPI 1: f32 + bias.
// ---------------------------------------------------------------------------
template <int EPI>
__global__ void __launch_bounds__(256)
hgemm(const __half* __restrict__ A_, const __half* __restrict__ B_,
      const float* __restrict__ bias, void* __restrict__ Cout,
      int M, int N, int K)
{
    __shared__ __half sA[2][128 * 16];
    __shared__ __half sB[2][16 * 128];

    int tid  = threadIdx.x;
    int lane = tid & 31, wid = tid >> 5;
    int g = lane >> 2, tig = lane & 3;
    int warpM = wid >> 2, warpN = wid & 3;
    int bm0 = blockIdx.y * 128, bn0 = blockIdx.x * 128;

    float acc[4][4][4];
    #pragma unroll
    for (int a = 0; a < 4; a++)
        #pragma unroll
        for (int b = 0; b < 4; b++)
            #pragma unroll
            for (int c = 0; c < 4; c++) acc[a][b][c] = 0.f;

    const int NT = K / 16;

    int am = tid >> 1, akc = tid & 1;          // A: row, k-chunk of 8
    int aoff = am * 32 + 16 * (akc ^ ((am >> 2) & 1));
    int bk = tid >> 4, bnc = tid & 15;         // B: k-row, n-chunk of 8
    int boff = bk * 256 + 16 * (bnc ^ (bk & 7));

    auto issue = [&](int kt, int buf) {
        int k0 = kt * 16;
        cpasync16((char*)sA[buf] + aoff, A_ + (size_t)(bm0 + am) * K + k0 + akc * 8);
        cpasync16((char*)sB[buf] + boff, B_ + (size_t)(k0 + bk) * N + bn0 + bnc * 8);
        asm volatile("cp.async.commit_group;\n");
    };

    int a_m  = ((lane >> 3) & 1) * 8 + (lane & 7);
    int a_kc = lane >> 4;
    int b_k  = ((lane >> 3) & 1) * 8 + (lane & 7);
    int b_n8 = lane >> 4;

    issue(0, 0);

    for (int kt = 0; kt < NT; kt++) {
        int cur = kt & 1;
        if (kt + 1 < NT) {
            issue(kt + 1, cur ^ 1);
            asm volatile("cp.async.wait_group 1;\n");
        } else {
            asm volatile("cp.async.wait_group 0;\n");
        }
        __syncthreads();

        uint32_t fa[4][4];
        #pragma unroll
        for (int mt = 0; mt < 4; mt++) {
            int m = warpM * 64 + mt * 16 + a_m;
            int off = m * 32 + 16 * (a_kc ^ ((m >> 2) & 1));
            ldsm_x4((uint32_t)__cvta_generic_to_shared((char*)sA[cur] + off), fa[mt]);
        }
        uint32_t fb[2][4];
        #pragma unroll
        for (int p = 0; p < 2; p++) {
            int n = warpN * 32 + p * 16 + b_n8 * 8;
            int off = b_k * 256 + 16 * ((n >> 3) ^ (b_k & 7));
            ldsm_x4_t((uint32_t)__cvta_generic_to_shared((char*)sB[cur] + off), fb[p]);
        }
        __syncthreads();

        #pragma unroll
        for (int mt = 0; mt < 4; mt++)
            #pragma unroll
            for (int nt = 0; nt < 4; nt++) {
                int p = nt >> 1, s2 = (nt & 1) * 2;
                uint32_t bb[2] = { fb[p][s2], fb[p][s2 + 1] };
                mma_f16(acc[mt][nt], fa[mt], bb);
            }
    }

    if (EPI == 0) {
        __half* C = (__half*)Cout;
        float scale = (bn0 < CDIM) ? 0.18033688011112042f : 1.0f;  // 0.125*log2e
        #pragma unroll
        for (int mt = 0; mt < 4; mt++) {
            int row0 = bm0 + warpM * 64 + mt * 16 + g;
            #pragma unroll
            for (int nt = 0; nt < 4; nt++) {
                int col = bn0 + warpN * 32 + nt * 8 + 2 * tig;
                *(__half2*)(C + (size_t)row0 * N + col) =
                    __floats2half2_rn(acc[mt][nt][0] * scale, acc[mt][nt][1] * scale);
                *(__half2*)(C + (size_t)(row0 + 8) * N + col) =
                    __floats2half2_rn(acc[mt][nt][2] * scale, acc[mt][nt][3] * scale);
            }
        }
    } else {
        float* C = (float*)Cout;
        #pragma unroll
        for (int mt = 0; mt < 4; mt++) {
            int row0 = bm0 + warpM * 64 + mt * 16 + g;
            #pragma unroll
            for (int nt = 0; nt < 4; nt++) {
                int col = bn0 + warpN * 32 + nt * 8 + 2 * tig;
                float b0 = bias[col], b1 = bias[col + 1];
                float2 v0 = { acc[mt][nt][0] + b0, acc[mt][nt][1] + b1 };
                float2 v1 = { acc[mt][nt][2] + b0, acc[mt][nt][3] + b1 };
                *(float2*)(C + (size_t)row0 * N + col) = v0;
                *(float2*)(C + (size_t)(row0 + 8) * N + col) = v1;
            }
        }
    }
}

// ---------------------------------------------------------------------------
// Flash attention, all-fp16 operands, fp32 accum. S: fp16 k16 mma with
// swizzled ldmatrix frags. Softmax in exp2 domain (log2e folded into Q).
// PV: fp16 mma, P repacked from C-frags, V via swizzled ldmatrix.trans.
// Output: att as single fp16 (input to hgemm<1>).
// ---------------------------------------------------------------------------
__global__ void __launch_bounds__(128)
flash_mma(const __half* __restrict__ qkv, const __half* __restrict__ vsrc,
          __half* __restrict__ outf)
{
    extern __shared__ char smc[];
    char* Qs  = smc;                  // 128 x 128B (fp16, swizzled)
    char* Kb0 = Qs + 128 * 128;       // 2 x 64 x 128B
    char* Vb0 = Kb0 + 2 * 64 * 128;   // 2 x 64 x 128B

    int tid  = threadIdx.x;
    int lane = tid & 31, wid = tid >> 5;
    int g = lane >> 2, tig = lane & 3;
    int h  = blockIdx.y;
    int q0 = blockIdx.x * 128;
    int wr = wid * 32;

    auto issue_kv = [&](int t, int buf) {
        int kv0 = t * 64;
        char* Kb = Kb0 + buf * 64 * 128;
        char* Vb = Vb0 + buf * 64 * 128;
        #pragma unroll
        for (int i = 0; i < 4; i++) {
            int idx = i * 128 + tid;
            int r = idx >> 3, c8 = (idx & 7) * 8;
            int sw = 16 * ((c8 >> 3) ^ (r & 7));
            cpasync16(Kb + r * 128 + sw,
                      qkv + (size_t)(kv0 + r) * 2048 + 1024 + h * 64 + c8);
            cpasync16(Vb + r * 128 + sw,
                      vsrc + (size_t)(kv0 + r) * 1024 + h * 64 + c8);
        }
        asm volatile("cp.async.commit_group;\n");
    };

    issue_kv(0, 0);
    #pragma unroll
    for (int i = 0; i < 8; i++) {
        int idx = i * 128 + tid;
        int r = idx >> 3, c8 = (idx & 7) * 8;
        cpasync16(Qs + r * 128 + 16 * ((c8 >> 3) ^ (r & 7)),
                  qkv + (size_t)(q0 + r) * 2048 + h * 64 + c8);
    }
    asm volatile("cp.async.commit_group;\n");

    float m_i[4], l_i[4], accO[2][8][4];
    #pragma unroll
    for (int i = 0; i < 4; i++) { m_i[i] = -1e30f; l_i[i] = 0.f; }
    #pragma unroll
    for (int mt = 0; mt < 2; mt++)
        #pragma unroll
        for (int dn = 0; dn < 8; dn++)
            #pragma unroll
            for (int c = 0; c < 4; c++) accO[mt][dn][c] = 0.f;

    int lm_row = ((lane >> 3) & 1) * 8 + (lane & 7);
    int lm_k8  = lane >> 4;

    for (int t = 0; t < SEQ / 64; t++) {
        int cur = t & 1;
        if (t + 1 < SEQ / 64) {
            issue_kv(t + 1, cur ^ 1);
            asm volatile("cp.async.wait_group 1;\n");
        } else {
            asm volatile("cp.async.wait_group 0;\n");
        }
        __syncthreads();

        char* Kb = Kb0 + cur * 64 * 128;
        char* Vb = Vb0 + cur * 64 * 128;

        // ---- S = Q @ K^T ----
        float s[2][8][4];
        #pragma unroll
        for (int mt = 0; mt < 2; mt++)
            #pragma unroll
            for (int nt = 0; nt < 8; nt++)
                #pragma unroll
                for (int c = 0; c < 4; c++) s[mt][nt][c] = 0.f;

        #pragma unroll
        for (int kc = 0; kc < 4; kc++) {
            uint32_t qa[2][4];
            #pragma unroll
            for (int mt = 0; mt < 2; mt++) {
                int m = wr + mt * 16 + lm_row;
                uint32_t addr = (uint32_t)__cvta_generic_to_shared(
                    Qs + m * 128 + 16 * ((kc * 2 + lm_k8) ^ (m & 7)));
                ldsm_x4(addr, qa[mt]);
            }
            #pragma unroll
            for (int ntp = 0; ntp < 4; ntp++) {
                int n = ntp * 16 + lm_row;
                uint32_t kb4[4];
                uint32_t addr = (uint32_t)__cvta_generic_to_shared(
                    Kb + n * 128 + 16 * ((kc * 2 + lm_k8) ^ (n & 7)));
                ldsm_x4(addr, kb4);
                uint32_t be[2] = { kb4[0], kb4[2] };
                uint32_t bo[2] = { kb4[1], kb4[3] };
                mma_f16(s[0][2 * ntp],     qa[0], be);
                mma_f16(s[0][2 * ntp + 1], qa[0], bo);
                mma_f16(s[1][2 * ntp],     qa[1], be);
                mma_f16(s[1][2 * ntp + 1], qa[1], bo);
            }
        }

        // ---- online softmax (exp2 domain) ----
        #pragma unroll
        for (int mt = 0; mt < 2; mt++)
            #pragma unroll
            for (int rg = 0; rg < 2; rg++) {
                int ri = mt * 2 + rg;
                float mx = -1e30f;
                #pragma unroll
                for (int nt = 0; nt < 8; nt++) {
                    mx = fmaxf(mx, s[mt][nt][2 * rg]);
                    mx = fmaxf(mx, s[mt][nt][2 * rg + 1]);
                }
                mx = fmaxf(mx, __shfl_xor_sync(0xffffffffu, mx, 1));
                mx = fmaxf(mx, __shfl_xor_sync(0xffffffffu, mx, 2));
                float mnew = fmaxf(m_i[ri], mx);
                float corr = exp2f(m_i[ri] - mnew);
                m_i[ri] = mnew;
                float rs = 0.f;
                #pragma unroll
                for (int nt = 0; nt < 8; nt++) {
                    float p0 = exp2f(s[mt][nt][2 * rg]     - mnew);
                    float p1 = exp2f(s[mt][nt][2 * rg + 1] - mnew);
                    s[mt][nt][2 * rg]     = p0;
                    s[mt][nt][2 * rg + 1] = p1;
                    rs += p0 + p1;
                }
                rs += __shfl_xor_sync(0xffffffffu, rs, 1);
                rs += __shfl_xor_sync(0xffffffffu, rs, 2);
                l_i[ri] = l_i[ri] * corr + rs;
                #pragma unroll
                for (int dn = 0; dn < 8; dn++) {
                    accO[mt][dn][2 * rg]     *= corr;
                    accO[mt][dn][2 * rg + 1] *= corr;
                }
            }

        // ---- O += P @ V ----
        #pragma unroll
        for (int kc = 0; kc < 4; kc++) {
            uint32_t pa[2][4];
            #pragma unroll
            for (int mt = 0; mt < 2; mt++) {
                pa[mt][0] = packh2(s[mt][2 * kc][0],     s[mt][2 * kc][1]);
                pa[mt][1] = packh2(s[mt][2 * kc][2],     s[mt][2 * kc][3]);
                pa[mt][2] = packh2(s[mt][2 * kc + 1][0], s[mt][2 * kc + 1][1]);
                pa[mt][3] = packh2(s[mt][2 * kc + 1][2], s[mt][2 * kc + 1][3]);
            }
            #pragma unroll
            for (int dnp = 0; dnp < 4; dnp++) {
                int key = kc * 16 + lm_row;
                int d   = dnp * 16 + lm_k8 * 8;
                uint32_t vb4[4];
                uint32_t addr = (uint32_t)__cvta_generic_to_shared(
                    Vb + key * 128 + 16 * ((d >> 3) ^ (key & 7)));
                ldsm_x4_t(addr, vb4);
                uint32_t vlo[2] = { vb4[0], vb4[1] };
                uint32_t vhi[2] = { vb4[2], vb4[3] };
                mma_f16(accO[0][2 * dnp],     pa[0], vlo);
                mma_f16(accO[0][2 * dnp + 1], pa[0], vhi);
                mma_f16(accO[1][2 * dnp],     pa[1], vlo);
                mma_f16(accO[1][2 * dnp + 1], pa[1], vhi);
            }
        }
        __syncthreads();
    }

    // ---- epilogue: att as fp16 ----
    #pragma unroll
    for (int mt = 0; mt < 2; mt++)
        #pragma unroll
        for (int rg = 0; rg < 2; rg++) {
            int ri = mt * 2 + rg;
            float inv = 1.0f / l_i[ri];
            int r = q0 + wr + mt * 16 + g + rg * 8;
            #pragma unroll
            for (int dn = 0; dn < 8; dn++) {
                int col = h * 64 + dn * 8 + 2 * tig;
                *(__half2*)(outf + (size_t)r * CDIM + col) =
                    __floats2half2_rn(accO[mt][dn][2 * rg] * inv,
                                      accO[mt][dn][2 * rg + 1] * inv);
            }
        }
}

// ---------------------------------------------------------------------------
extern "C" void kernel_launch(void* const* d_in, const int* in_sizes, int n_in,
                              void* d_out, int out_size)
{
    const float* x1     = (const float*)d_in[0];
    const float* x2     = (const float*)d_in[1];
    const float* W_qkv  = (const float*)d_in[2];
    const float* W_proj = (const float*)d_in[3];
    const float* b_proj = (const float*)d_in[4];
    float* out = (float*)d_out;

    __half *qkvh, *vh, *x1f, *atf, *wqf, *wpf;
    cudaGetSymbolAddress((void**)&qkvh, g_qkvh);
    cudaGetSymbolAddress((void**)&vh,  g_vh);
    cudaGetSymbolAddress((void**)&x1f, g_x1f);
    cudaGetSymbolAddress((void**)&atf, g_atf);
    cudaGetSymbolAddress((void**)&wqf, g_wqf);
    cudaGetSymbolAddress((void**)&wpf, g_wpf);

    cvt_f16<<<SEQ * CDIM / 1024, 256>>>(x1, x1f, SEQ * CDIM);
    cvt_f16<<<2 * CDIM * CDIM / 1024, 256>>>(W_qkv, wqf, 2 * CDIM * CDIM);
    cvt_f16<<<CDIM * CDIM / 1024, 256>>>(W_proj, wpf, CDIM * CDIM);
    cvt_f16<<<SEQ * CDIM / 1024, 256>>>(x2, vh, SEQ * CDIM);

    // 1) qkv = x1 @ W_qkv (fp16, q scaled)
    {
        dim3 grid(2 * CDIM / 128, SEQ / 128);
        hgemm<0><<<grid, 256>>>(x1f, wqf, nullptr, qkvh, SEQ, 2 * CDIM, CDIM);
    }
    // 2) flash attention
    {
        int smem = 128 * 128 + 2 * 64 * 128 + 2 * 64 * 128;   // 48 KB
        cudaFuncSetAttribute(flash_mma,
                             cudaFuncAttributeMaxDynamicSharedMemorySize, smem);
        dim3 grid(SEQ / 128, NH);
        flash_mma<<<grid, 128, smem>>>(qkvh, vh, atf);
    }
    // 3) out = att @ W_proj + bias
    {
        dim3 grid(CDIM / 128, SEQ / 128);
        hgemm<1><<<grid, 256>>>(atf, wpf, b_proj, out, SEQ, CDIM, CDIM);
    }
}